// round 5
// baseline (speedup 1.0000x reference)
#include <cuda_runtime.h>
#include <cfloat>
#include <cstdint>
#include <climits>

#define BATCH   4096
#define HIST    50
#define NITEMS  100000
#define DIM     128
#define TOPK    21
#define ROWT    64                         // queries per CTA
#define ITEMT   128                        // items per chunk
#define NCHUNK  782                        // ceil(100000/128)
#define NSPLIT  37                         // 37*64 = 2368 CTAs = 8 waves @ 2/SM
#define FUSED_SMEM ((ROWT * DIM + ITEMT * DIM) * 4)   // 96 KB

// ---------------- static scratch (module-load; no runtime alloc) ------------
__device__ float g_query[BATCH * DIM];                         // 2 MB
__device__ float g_pv[(size_t)BATCH * NSPLIT * 4 * TOPK];      // ~51 MB
__device__ int   g_pi[(size_t)BATCH * NSPLIT * 4 * TOPK];      // ~51 MB

// ---------------- comparator: matches jax.lax.top_k (val desc, idx asc) -----
__device__ __forceinline__ bool better(float v1, int i1, float v2, int i2) {
    return (v1 > v2) || (v1 == v2 && i1 < i2);
}

// register-resident sorted insert; static indices only (no local-mem spill)
__device__ __forceinline__ void tk_insert(float (&tv)[TOPK], int (&ti)[TOPK],
                                          float v, int idx) {
    if (better(v, idx, tv[TOPK - 1], ti[TOPK - 1])) {
        tv[TOPK - 1] = v; ti[TOPK - 1] = idx;
        #pragma unroll
        for (int k = TOPK - 1; k > 0; --k) {
            bool sw = better(tv[k], ti[k], tv[k - 1], ti[k - 1]);
            float av = sw ? tv[k]     : tv[k - 1];
            float bv = sw ? tv[k - 1] : tv[k];
            int   ai = sw ? ti[k]     : ti[k - 1];
            int   bi = sw ? ti[k - 1] : ti[k];
            tv[k - 1] = av; tv[k] = bv;
            ti[k - 1] = ai; ti[k] = bi;
        }
    }
}

// ---------------- stage 1: masked mean-pool query build ---------------------
__global__ __launch_bounds__(DIM) void query_kernel(
    const int* __restrict__ item_seq,
    const int* __restrict__ item_seq_len,
    const float* __restrict__ emb)
{
    __shared__ int sidx[HIST];
    const int b = blockIdx.x;
    const int d = threadIdx.x;

    if (d < HIST) sidx[d] = item_seq[b * HIST + d];
    __syncthreads();

    const int len = item_seq_len[b];
    float s = 0.f;
    for (int l = 0; l < len; ++l) s += emb[(size_t)sidx[l] * DIM + d];
    const int denom = len > 1 ? len : 1;
    g_query[b * DIM + d] = s / (float)denom;
}

// ---------------- stage 2: fused scores GEMM + partial top-21 ---------------
// CTA: 64 rows x ~21 chunks of 128 items, K=128 resident. 256 threads.
// smem: As [k][row] 32KB (loaded once), Bs [k][item] 64KB (per chunk);
// Bs is reused between chunks as swizzled score buffer [item][row ^ f].
__global__ __launch_bounds__(256, 2) void fused_kernel(const float* __restrict__ emb)
{
    extern __shared__ float smem[];
    float* As = smem;                    // 128 x 64
    float* Bs = smem + ROWT * DIM;       // 128 x 128

    const int tid  = threadIdx.x;
    const int row6 = tid & 63;           // A-load / scan row
    const int qd   = tid >> 6;           // quarter (0..3)
    const int li   = tid & 127;          // B-load item lane
    const int lh   = tid >> 7;           // B-load k-half
    const int tx   = tid & 15;           // compute: item group (8 items)
    const int ty   = tid >> 4;           // compute: row group (4 rows)
    const int rowBase = blockIdx.y * ROWT;

    // ---- load A (queries) once, transposed to k-major; conflict-free STS
    #pragma unroll
    for (int r = 0; r < 8; ++r) {
        const int k4 = qd * 8 + r;
        float4 v = *(const float4*)&g_query[(size_t)(rowBase + row6) * DIM + k4 * 4];
        As[(k4 * 4 + 0) * ROWT + row6] = v.x;
        As[(k4 * 4 + 1) * ROWT + row6] = v.y;
        As[(k4 * 4 + 2) * ROWT + row6] = v.z;
        As[(k4 * 4 + 3) * ROWT + row6] = v.w;
    }

    // per-thread top-21 for (row = row6, item-quarter = qd) within this split
    float tv[TOPK];
    int   ti[TOPK];
    #pragma unroll
    for (int k = 0; k < TOPK; ++k) { tv[k] = -FLT_MAX; ti[k] = INT_MAX; }

    const int c0 = (blockIdx.x * NCHUNK) / NSPLIT;
    const int c1 = ((blockIdx.x + 1) * NCHUNK) / NSPLIT;

    for (int ch = c0; ch < c1; ++ch) {
        const int itemBase = ch * ITEMT;
        const int gi = itemBase + li;
        const bool ok = gi < NITEMS;

        // ---- load B chunk (128 emb rows) transposed to k-major; zero OOB
        #pragma unroll
        for (int r = 0; r < 16; ++r) {
            const int k4 = lh * 16 + r;
            float4 v = make_float4(0.f, 0.f, 0.f, 0.f);
            if (ok) v = *(const float4*)&emb[(size_t)gi * DIM + k4 * 4];
            Bs[(k4 * 4 + 0) * ITEMT + li] = v.x;
            Bs[(k4 * 4 + 1) * ITEMT + li] = v.y;
            Bs[(k4 * 4 + 2) * ITEMT + li] = v.z;
            Bs[(k4 * 4 + 3) * ITEMT + li] = v.w;
        }
        __syncthreads();

        // ---- 64x128 fp32 GEMM, micro 4x8
        float acc[4][8];
        #pragma unroll
        for (int i = 0; i < 4; ++i)
            #pragma unroll
            for (int j = 0; j < 8; ++j) acc[i][j] = 0.f;

        #pragma unroll 4
        for (int k = 0; k < DIM; ++k) {
            float4 a  = *(const float4*)&As[k * ROWT + ty * 4];
            float4 b0 = *(const float4*)&Bs[k * ITEMT + tx * 8];
            float4 b1 = *(const float4*)&Bs[k * ITEMT + tx * 8 + 4];
            float av[4] = {a.x, a.y, a.z, a.w};
            float bv[8] = {b0.x, b0.y, b0.z, b0.w, b1.x, b1.y, b1.z, b1.w};
            #pragma unroll
            for (int i = 0; i < 4; ++i)
                #pragma unroll
                for (int j = 0; j < 8; ++j)
                    acc[i][j] += av[i] * bv[j];
        }
        __syncthreads();   // all Bs reads done; safe to overwrite with scores

        // ---- stage scores into Bs as [item][row ^ f], f = ((tx+j)&7)*8.
        // f only touches bits >= 3, so the 4-aligned float4 store stays valid.
        #pragma unroll
        for (int j = 0; j < 8; ++j) {
            const int item = tx * 8 + j;
            const int f    = ((tx + j) & 7) * 8;
            const int rsw  = (ty * 4) ^ f;
            *(float4*)&Bs[item * ROWT + rsw] =
                make_float4(acc[0][j], acc[1][j], acc[2][j], acc[3][j]);
        }
        __syncthreads();

        // ---- scan: thread owns (row6, quarter qd); reads conflict-free
        #pragma unroll 4
        for (int s = 0; s < 32; ++s) {
            const int jj = qd * 32 + s;
            const int f  = (((jj >> 3) + (jj & 7)) & 7) * 8;
            const float val = Bs[jj * ROWT + (row6 ^ f)];
            const int gidx = itemBase + jj;
            if (gidx < NITEMS) tk_insert(tv, ti, val, gidx);
        }
        __syncthreads();   // scan done before next chunk overwrites Bs
    }

    // ---- write partial top-21 for (row, split, quarter)
    const size_t base =
        (((size_t)(rowBase + row6) * NSPLIT + blockIdx.x) * 4 + qd) * TOPK;
    #pragma unroll
    for (int k = 0; k < TOPK; ++k) {
        g_pv[base + k] = tv[k];
        g_pi[base + k] = ti[k];
    }
}

// ---------------- stage 3: merge partials -> global top-21 per row ----------
__global__ __launch_bounds__(256) void merge_kernel(float* __restrict__ out)
{
    __shared__ float sv[256 * TOPK];
    __shared__ int   si[256 * TOPK];
    __shared__ float rv[256];
    __shared__ int   ri[256];
    __shared__ int   ro[256];
    __shared__ int   hp[256];

    const int tid = threadIdx.x;
    const int row = blockIdx.x;
    const int NC  = NSPLIT * 4 * TOPK;       // 3108 candidates per row

    float tv[TOPK];
    int   ti[TOPK];
    #pragma unroll
    for (int k = 0; k < TOPK; ++k) { tv[k] = -FLT_MAX; ti[k] = INT_MAX; }

    const size_t rbase = (size_t)row * NC;
    for (int c = tid; c < NC; c += 256)
        tk_insert(tv, ti, g_pv[rbase + c], g_pi[rbase + c]);

    #pragma unroll
    for (int k = 0; k < TOPK; ++k) {
        sv[tid * TOPK + k] = tv[k];
        si[tid * TOPK + k] = ti[k];
    }
    hp[tid] = 0;
    __syncthreads();

    for (int sel = 0; sel < TOPK; ++sel) {
        const int p = hp[tid];
        rv[tid] = sv[tid * TOPK + p];
        ri[tid] = si[tid * TOPK + p];
        ro[tid] = tid;
        __syncthreads();
        for (int s = 128; s > 0; s >>= 1) {
            if (tid < s) {
                if (better(rv[tid + s], ri[tid + s], rv[tid], ri[tid])) {
                    rv[tid] = rv[tid + s];
                    ri[tid] = ri[tid + s];
                    ro[tid] = ro[tid + s];
                }
            }
            __syncthreads();
        }
        if (tid == 0) {
            out[row * TOPK + sel] = rv[0];                               // values
            out[(size_t)BATCH * TOPK + row * TOPK + sel] = (float)ri[0]; // indices
            hp[ro[0]]++;
        }
        __syncthreads();
    }
}

// ---------------- launch -----------------------------------------------------
extern "C" void kernel_launch(void* const* d_in, const int* in_sizes, int n_in,
                              void* d_out, int out_size)
{
    const int*   item_seq     = (const int*)d_in[0];
    const int*   item_seq_len = (const int*)d_in[1];
    const float* emb          = (const float*)d_in[2];
    float*       out          = (float*)d_out;

    static bool attr_done = false;
    if (!attr_done) {
        cudaFuncSetAttribute(fused_kernel,
                             cudaFuncAttributeMaxDynamicSharedMemorySize,
                             FUSED_SMEM);
        attr_done = true;
    }

    query_kernel<<<BATCH, DIM>>>(item_seq, item_seq_len, emb);
    fused_kernel<<<dim3(NSPLIT, BATCH / ROWT), 256, FUSED_SMEM>>>(emb);
    merge_kernel<<<BATCH, 256>>>(out);
}

// round 8
// speedup vs baseline: 1.0024x; 1.0024x over previous
#include <cuda_runtime.h>
#include <cfloat>
#include <cstdint>
#include <climits>

#define BATCH   4096
#define HIST    50
#define NITEMS  100000
#define DIM     128
#define TOPK    21
#define ROWT    64                         // queries per CTA
#define ITEMT   128                        // items per chunk
#define NCHUNK  782                        // ceil(100000/128)
#define NSPLIT  37                         // 37*64 = 2368 CTAs = 8 waves @ 2/SM
#define FUSED_SMEM ((ROWT * DIM + ITEMT * DIM) * 4)   // 96 KB dynamic

// ---------------- static scratch (module-load; no runtime alloc) ------------
__device__ float g_query[BATCH * DIM];                         // 2 MB
__device__ float g_pv[(size_t)BATCH * NSPLIT * 4 * TOPK];      // ~51 MB
__device__ int   g_pi[(size_t)BATCH * NSPLIT * 4 * TOPK];      // ~51 MB

// ---------------- comparator: matches jax.lax.top_k (val desc, idx asc) -----
__device__ __forceinline__ bool better(float v1, int i1, float v2, int i2) {
    return (v1 > v2) || (v1 == v2 && i1 < i2);
}

// register-resident sorted insert; static indices only (no local-mem spill)
__device__ __forceinline__ void tk_insert(float (&tv)[TOPK], int (&ti)[TOPK],
                                          float v, int idx) {
    if (better(v, idx, tv[TOPK - 1], ti[TOPK - 1])) {
        tv[TOPK - 1] = v; ti[TOPK - 1] = idx;
        #pragma unroll
        for (int k = TOPK - 1; k > 0; --k) {
            bool sw = better(tv[k], ti[k], tv[k - 1], ti[k - 1]);
            float av = sw ? tv[k]     : tv[k - 1];
            float bv = sw ? tv[k - 1] : tv[k];
            int   ai = sw ? ti[k]     : ti[k - 1];
            int   bi = sw ? ti[k - 1] : ti[k];
            tv[k - 1] = av; tv[k] = bv;
            ti[k - 1] = ai; ti[k] = bi;
        }
    }
}

// ---------------- stage 1: masked mean-pool query build ---------------------
__global__ __launch_bounds__(DIM) void query_kernel(
    const int* __restrict__ item_seq,
    const int* __restrict__ item_seq_len,
    const float* __restrict__ emb)
{
    __shared__ int sidx[HIST];
    const int b = blockIdx.x;
    const int d = threadIdx.x;

    if (d < HIST) sidx[d] = item_seq[b * HIST + d];
    __syncthreads();

    const int len = item_seq_len[b];
    float s = 0.f;
    for (int l = 0; l < len; ++l) s += emb[(size_t)sidx[l] * DIM + d];
    const int denom = len > 1 ? len : 1;
    g_query[b * DIM + d] = s / (float)denom;
}

// ---------------- stage 2: fused scores GEMM + partial top-21 ---------------
// CTA: 64 rows x ~21 chunks of 128 items, K=128 resident. 256 threads.
// smem: As [k][row] 32KB (loaded once), Bs [k][item] 64KB (per chunk);
// Bs reused between chunks as swizzled score buffer [item][row ^ f].
// Per-row running threshold (max of the 4 owning threads' local 21st-best)
// filters the scan so the expensive insert chain fires only on true inserts.
__global__ __launch_bounds__(256, 2) void fused_kernel(const float* __restrict__ emb)
{
    extern __shared__ float smem[];
    float* As = smem;                    // 128 x 64
    float* Bs = smem + ROWT * DIM;       // 128 x 128

    __shared__ float st_v[256];          // per-thread published 21st value
    __shared__ int   st_i[256];          // per-thread published 21st index

    const int tid  = threadIdx.x;
    const int row6 = tid & 63;           // A-load / scan row
    const int qd   = tid >> 6;           // quarter (0..3)
    const int li   = tid & 127;          // B-load item lane
    const int lh   = tid >> 7;           // B-load k-half
    const int tx   = tid & 15;           // compute: item group (8 items)
    const int ty   = tid >> 4;           // compute: row group (4 rows)
    const int rowBase = blockIdx.y * ROWT;

    // ---- load A (queries) once, transposed to k-major; conflict-free STS
    #pragma unroll
    for (int r = 0; r < 8; ++r) {
        const int k4 = qd * 8 + r;
        float4 v = *(const float4*)&g_query[(size_t)(rowBase + row6) * DIM + k4 * 4];
        As[(k4 * 4 + 0) * ROWT + row6] = v.x;
        As[(k4 * 4 + 1) * ROWT + row6] = v.y;
        As[(k4 * 4 + 2) * ROWT + row6] = v.z;
        As[(k4 * 4 + 3) * ROWT + row6] = v.w;
    }

    // per-thread top-21 for (row = row6, item-quarter = qd) within this split
    float tv[TOPK];
    int   ti[TOPK];
    #pragma unroll
    for (int k = 0; k < TOPK; ++k) { tv[k] = -FLT_MAX; ti[k] = INT_MAX; }

    // per-row filter threshold (register copy, rebuilt each chunk)
    float thrv = -FLT_MAX;
    int   thri = INT_MAX;

    const int c0 = (blockIdx.x * NCHUNK) / NSPLIT;
    const int c1 = ((blockIdx.x + 1) * NCHUNK) / NSPLIT;

    for (int ch = c0; ch < c1; ++ch) {
        const int itemBase = ch * ITEMT;
        const int gi = itemBase + li;
        const bool ok = gi < NITEMS;

        // ---- load B chunk (128 emb rows) transposed to k-major; zero OOB
        #pragma unroll
        for (int r = 0; r < 16; ++r) {
            const int k4 = lh * 16 + r;
            float4 v = make_float4(0.f, 0.f, 0.f, 0.f);
            if (ok) v = *(const float4*)&emb[(size_t)gi * DIM + k4 * 4];
            Bs[(k4 * 4 + 0) * ITEMT + li] = v.x;
            Bs[(k4 * 4 + 1) * ITEMT + li] = v.y;
            Bs[(k4 * 4 + 2) * ITEMT + li] = v.z;
            Bs[(k4 * 4 + 3) * ITEMT + li] = v.w;
        }
        __syncthreads();

        // ---- 64x128 fp32 GEMM, micro 4x8
        float acc[4][8];
        #pragma unroll
        for (int i = 0; i < 4; ++i)
            #pragma unroll
            for (int j = 0; j < 8; ++j) acc[i][j] = 0.f;

        #pragma unroll 8
        for (int k = 0; k < DIM; ++k) {
            float4 a  = *(const float4*)&As[k * ROWT + ty * 4];
            float4 b0 = *(const float4*)&Bs[k * ITEMT + tx * 8];
            float4 b1 = *(const float4*)&Bs[k * ITEMT + tx * 8 + 4];
            float av[4] = {a.x, a.y, a.z, a.w};
            float bv[8] = {b0.x, b0.y, b0.z, b0.w, b1.x, b1.y, b1.z, b1.w};
            #pragma unroll
            for (int i = 0; i < 4; ++i)
                #pragma unroll
                for (int j = 0; j < 8; ++j)
                    acc[i][j] += av[i] * bv[j];
        }
        __syncthreads();   // all Bs reads done; safe to overwrite with scores

        // ---- stage scores into Bs as [item][row ^ f], f = ((tx+j)&7)*8.
        // f only touches bits >= 3, so the 4-aligned float4 store stays valid.
        #pragma unroll
        for (int j = 0; j < 8; ++j) {
            const int item = tx * 8 + j;
            const int f    = ((tx + j) & 7) * 8;
            const int rsw  = (ty * 4) ^ f;
            *(float4*)&Bs[item * ROWT + rsw] =
                make_float4(acc[0][j], acc[1][j], acc[2][j], acc[3][j]);
        }
        __syncthreads();

        // ---- scan: thread owns (row6, quarter qd); reads conflict-free.
        // Threshold filter keeps the insert chain cold after the first chunk.
        #pragma unroll 4
        for (int s = 0; s < 32; ++s) {
            const int jj = qd * 32 + s;
            const int f  = (((jj >> 3) + (jj & 7)) & 7) * 8;
            const float val = Bs[jj * ROWT + (row6 ^ f)];
            const int gidx = itemBase + jj;
            if (gidx < NITEMS && better(val, gidx, thrv, thri))
                tk_insert(tv, ti, val, gidx);
        }

        // ---- publish local 21st-best; rebuild per-row threshold
        st_v[tid] = tv[TOPK - 1];
        st_i[tid] = ti[TOPK - 1];
        __syncthreads();   // also protects Bs before next chunk's B-load
        {
            float bv0 = st_v[row6];       int bi0 = st_i[row6];
            #pragma unroll
            for (int q = 1; q < 4; ++q) {
                float cv = st_v[row6 + 64 * q];
                int   ci = st_i[row6 + 64 * q];
                if (better(cv, ci, bv0, bi0)) { bv0 = cv; bi0 = ci; }
            }
            thrv = bv0; thri = bi0;
        }
        __syncthreads();   // st_* reads done before next chunk's publish
    }

    // ---- write partial top-21 for (row, split, quarter)
    const size_t base =
        (((size_t)(rowBase + row6) * NSPLIT + blockIdx.x) * 4 + qd) * TOPK;
    #pragma unroll
    for (int k = 0; k < TOPK; ++k) {
        g_pv[base + k] = tv[k];
        g_pi[base + k] = ti[k];
    }
}

// ---------------- stage 3: merge partials -> global top-21 per row ----------
__global__ __launch_bounds__(256) void merge_kernel(float* __restrict__ out)
{
    __shared__ float sv[256 * TOPK];
    __shared__ int   si[256 * TOPK];
    __shared__ float rv[256];
    __shared__ int   ri[256];
    __shared__ int   ro[256];
    __shared__ int   hp[256];

    const int tid = threadIdx.x;
    const int row = blockIdx.x;
    const int NC  = NSPLIT * 4 * TOPK;       // 3108 candidates per row

    float tv[TOPK];
    int   ti[TOPK];
    #pragma unroll
    for (int k = 0; k < TOPK; ++k) { tv[k] = -FLT_MAX; ti[k] = INT_MAX; }

    const size_t rbase = (size_t)row * NC;
    for (int c = tid; c < NC; c += 256)
        tk_insert(tv, ti, g_pv[rbase + c], g_pi[rbase + c]);

    #pragma unroll
    for (int k = 0; k < TOPK; ++k) {
        sv[tid * TOPK + k] = tv[k];
        si[tid * TOPK + k] = ti[k];
    }
    hp[tid] = 0;
    __syncthreads();

    for (int sel = 0; sel < TOPK; ++sel) {
        const int p = hp[tid];
        rv[tid] = sv[tid * TOPK + p];
        ri[tid] = si[tid * TOPK + p];
        ro[tid] = tid;
        __syncthreads();
        for (int s = 128; s > 0; s >>= 1) {
            if (tid < s) {
                if (better(rv[tid + s], ri[tid + s], rv[tid], ri[tid])) {
                    rv[tid] = rv[tid + s];
                    ri[tid] = ri[tid + s];
                    ro[tid] = ro[tid + s];
                }
            }
            __syncthreads();
        }
        if (tid == 0) {
            out[row * TOPK + sel] = rv[0];                               // values
            out[(size_t)BATCH * TOPK + row * TOPK + sel] = (float)ri[0]; // indices
            hp[ro[0]]++;
        }
        __syncthreads();
    }
}

// ---------------- launch -----------------------------------------------------
extern "C" void kernel_launch(void* const* d_in, const int* in_sizes, int n_in,
                              void* d_out, int out_size)
{
    const int*   item_seq     = (const int*)d_in[0];
    const int*   item_seq_len = (const int*)d_in[1];
    const float* emb          = (const float*)d_in[2];
    float*       out          = (float*)d_out;

    cudaFuncSetAttribute(fused_kernel,
                         cudaFuncAttributeMaxDynamicSharedMemorySize,
                         FUSED_SMEM);

    query_kernel<<<BATCH, DIM>>>(item_seq, item_seq_len, emb);
    fused_kernel<<<dim3(NSPLIT, BATCH / ROWT), 256, FUSED_SMEM>>>(emb);
    merge_kernel<<<BATCH, 256>>>(out);
}

// round 10
// speedup vs baseline: 1.2561x; 1.2530x over previous
#include <cuda_runtime.h>
#include <cfloat>
#include <cstdint>
#include <climits>

#define BATCH   4096
#define HIST    50
#define NITEMS  100000
#define DIM     128
#define TOPK    21
#define ROWT    64                         // queries per CTA
#define ITEMT   128                        // items per chunk
#define NCHUNK  782                        // ceil(100000/128)
#define NSPLIT  37                         // 37*64 = 2368 CTAs = 8 waves @ 2/SM
#define CDEPTH  6                          // per-thread candidate stack depth
#define FUSED_SMEM ((ROWT * DIM + ITEMT * DIM) * 4)   // 96 KB dynamic

// ---------------- static scratch (module-load; no runtime alloc) ------------
__device__ float g_query[BATCH * DIM];                         // 2 MB
__device__ float g_pv[(size_t)BATCH * NSPLIT * 4 * TOPK];      // ~51 MB
__device__ int   g_pi[(size_t)BATCH * NSPLIT * 4 * TOPK];      // ~51 MB

// ---------------- comparator: matches jax.lax.top_k (val desc, idx asc) -----
__device__ __forceinline__ bool better(float v1, int i1, float v2, int i2) {
    return (v1 > v2) || (v1 == v2 && i1 < i2);
}

// register-resident sorted insert; static indices only (no local-mem spill)
__device__ __forceinline__ void tk_insert(float (&tv)[TOPK], int (&ti)[TOPK],
                                          float v, int idx) {
    if (better(v, idx, tv[TOPK - 1], ti[TOPK - 1])) {
        tv[TOPK - 1] = v; ti[TOPK - 1] = idx;
        #pragma unroll
        for (int k = TOPK - 1; k > 0; --k) {
            bool sw = better(tv[k], ti[k], tv[k - 1], ti[k - 1]);
            float av = sw ? tv[k]     : tv[k - 1];
            float bv = sw ? tv[k - 1] : tv[k];
            int   ai = sw ? ti[k]     : ti[k - 1];
            int   bi = sw ? ti[k - 1] : ti[k];
            tv[k - 1] = av; tv[k] = bv;
            ti[k - 1] = ai; ti[k] = bi;
        }
    }
}

// ---------------- stage 1: masked mean-pool query build ---------------------
__global__ __launch_bounds__(DIM) void query_kernel(
    const int* __restrict__ item_seq,
    const int* __restrict__ item_seq_len,
    const float* __restrict__ emb)
{
    __shared__ int sidx[HIST];
    const int b = blockIdx.x;
    const int d = threadIdx.x;

    if (d < HIST) sidx[d] = item_seq[b * HIST + d];
    __syncthreads();

    const int len = item_seq_len[b];
    float s = 0.f;
    for (int l = 0; l < len; ++l) s += emb[(size_t)sidx[l] * DIM + d];
    const int denom = len > 1 ? len : 1;
    g_query[b * DIM + d] = s / (float)denom;
}

// ---------------- stage 2: fused scores GEMM + partial top-21 ---------------
// GEMM inner loop uses packed fp32x2 FMA (fma.rn.f32x2): accumulators packed
// over item pairs (loaded straight from smem via ld.shared.v2.u64), row
// scalars replicated with mov.b64 {r,r}. Bitwise-identical to scalar FFMA.
// Scan: threshold compare only in the hot loop; passing candidates go to a
// per-thread smem stack and are drained through the register top-21 chain
// after the chunk (warp pays max-lane count, not any-lane-hit iterations).
__global__ __launch_bounds__(256, 2) void fused_kernel(const float* __restrict__ emb)
{
    extern __shared__ float smem[];
    float* As = smem;                    // 128 x 64
    float* Bs = smem + ROWT * DIM;       // 128 x 128

    __shared__ float st_v[256];          // per-thread published 21st value
    __shared__ int   st_i[256];          // per-thread published 21st index
    __shared__ float cd_v[256 * CDEPTH]; // candidate stacks (6 KB)
    __shared__ int   cd_i[256 * CDEPTH]; // candidate stacks (6 KB)

    const int tid  = threadIdx.x;
    const int row6 = tid & 63;           // A-load / scan row
    const int qd   = tid >> 6;           // quarter (0..3)
    const int li   = tid & 127;          // B-load item lane
    const int lh   = tid >> 7;           // B-load k-half
    const int tx   = tid & 15;           // compute: item group (8 items)
    const int ty   = tid >> 4;           // compute: row group (4 rows)
    const int rowBase = blockIdx.y * ROWT;

    const uint32_t bsAddr =
        (uint32_t)__cvta_generic_to_shared(Bs) + (uint32_t)(tx * 8) * 4u;

    // ---- load A (queries) once, transposed to k-major; conflict-free STS
    #pragma unroll
    for (int r = 0; r < 8; ++r) {
        const int k4 = qd * 8 + r;
        float4 v = *(const float4*)&g_query[(size_t)(rowBase + row6) * DIM + k4 * 4];
        As[(k4 * 4 + 0) * ROWT + row6] = v.x;
        As[(k4 * 4 + 1) * ROWT + row6] = v.y;
        As[(k4 * 4 + 2) * ROWT + row6] = v.z;
        As[(k4 * 4 + 3) * ROWT + row6] = v.w;
    }

    // per-thread top-21 for (row = row6, item-quarter = qd) within this split
    float tv[TOPK];
    int   ti[TOPK];
    #pragma unroll
    for (int k = 0; k < TOPK; ++k) { tv[k] = -FLT_MAX; ti[k] = INT_MAX; }

    // per-row filter threshold (register copy, rebuilt each chunk)
    float thrv = -FLT_MAX;
    int   thri = INT_MAX;

    const int c0 = (blockIdx.x * NCHUNK) / NSPLIT;
    const int c1 = ((blockIdx.x + 1) * NCHUNK) / NSPLIT;

    for (int ch = c0; ch < c1; ++ch) {
        const int itemBase = ch * ITEMT;
        const int gi = itemBase + li;
        const bool ok = gi < NITEMS;

        // ---- load B chunk (128 emb rows) transposed to k-major; zero OOB
        #pragma unroll
        for (int r = 0; r < 16; ++r) {
            const int k4 = lh * 16 + r;
            float4 v = make_float4(0.f, 0.f, 0.f, 0.f);
            if (ok) v = *(const float4*)&emb[(size_t)gi * DIM + k4 * 4];
            Bs[(k4 * 4 + 0) * ITEMT + li] = v.x;
            Bs[(k4 * 4 + 1) * ITEMT + li] = v.y;
            Bs[(k4 * 4 + 2) * ITEMT + li] = v.z;
            Bs[(k4 * 4 + 3) * ITEMT + li] = v.w;
        }
        __syncthreads();

        // ---- 64x128 fp32 GEMM, micro 4 rows x 8 items, f32x2-packed over items
        unsigned long long acc2[4][4];
        #pragma unroll
        for (int i = 0; i < 4; ++i)
            #pragma unroll
            for (int j = 0; j < 4; ++j) acc2[i][j] = 0ULL;

        #pragma unroll 8
        for (int k = 0; k < DIM; ++k) {
            const float4 a = *(const float4*)&As[k * ROWT + ty * 4];
            unsigned long long b0, b1, b2, b3;
            const uint32_t ba = bsAddr + (uint32_t)(k * ITEMT) * 4u;
            asm volatile("ld.shared.v2.u64 {%0,%1},[%2];"
                         : "=l"(b0), "=l"(b1) : "r"(ba));
            asm volatile("ld.shared.v2.u64 {%0,%1},[%2];"
                         : "=l"(b2), "=l"(b3) : "r"(ba + 16u));
            const float av[4] = {a.x, a.y, a.z, a.w};
            #pragma unroll
            for (int i = 0; i < 4; ++i) {
                unsigned long long ar;
                asm("mov.b64 %0,{%1,%1};" : "=l"(ar) : "r"(__float_as_uint(av[i])));
                asm("fma.rn.f32x2 %0,%1,%2,%0;" : "+l"(acc2[i][0]) : "l"(ar), "l"(b0));
                asm("fma.rn.f32x2 %0,%1,%2,%0;" : "+l"(acc2[i][1]) : "l"(ar), "l"(b1));
                asm("fma.rn.f32x2 %0,%1,%2,%0;" : "+l"(acc2[i][2]) : "l"(ar), "l"(b2));
                asm("fma.rn.f32x2 %0,%1,%2,%0;" : "+l"(acc2[i][3]) : "l"(ar), "l"(b3));
            }
        }

        // unpack packed accumulators to scalars
        float accf[4][8];
        #pragma unroll
        for (int i = 0; i < 4; ++i)
            #pragma unroll
            for (int j = 0; j < 4; ++j) {
                uint32_t lo, hi;
                asm("mov.b64 {%0,%1},%2;" : "=r"(lo), "=r"(hi) : "l"(acc2[i][j]));
                accf[i][2 * j]     = __uint_as_float(lo);
                accf[i][2 * j + 1] = __uint_as_float(hi);
            }
        __syncthreads();   // all Bs reads done; safe to overwrite with scores

        // ---- stage scores into Bs as [item][row ^ f], f = ((tx+j)&7)*8.
        #pragma unroll
        for (int j = 0; j < 8; ++j) {
            const int item = tx * 8 + j;
            const int f    = ((tx + j) & 7) * 8;
            const int rsw  = (ty * 4) ^ f;
            *(float4*)&Bs[item * ROWT + rsw] =
                make_float4(accf[0][j], accf[1][j], accf[2][j], accf[3][j]);
        }
        __syncthreads();

        // ---- scan: thread owns (row6, quarter qd); reads conflict-free.
        if (ch == c0) {
            // first chunk: threshold is -inf, every lane inserts -> direct path
            #pragma unroll 4
            for (int s = 0; s < 32; ++s) {
                const int jj = qd * 32 + s;
                const int f  = (((jj >> 3) + (jj & 7)) & 7) * 8;
                const float val = Bs[jj * ROWT + (row6 ^ f)];
                const int gidx = itemBase + jj;
                if (gidx < NITEMS) tk_insert(tv, ti, val, gidx);
            }
        } else {
            // hot path: compare + rare push; defer chain to drain phase
            int cnt = 0;
            #pragma unroll 4
            for (int s = 0; s < 32; ++s) {
                const int jj = qd * 32 + s;
                const int f  = (((jj >> 3) + (jj & 7)) & 7) * 8;
                const float val = Bs[jj * ROWT + (row6 ^ f)];
                const int gidx = itemBase + jj;
                if (gidx < NITEMS && better(val, gidx, thrv, thri)) {
                    if (cnt < CDEPTH) {
                        cd_v[tid * CDEPTH + cnt] = val;
                        cd_i[tid * CDEPTH + cnt] = gidx;
                        ++cnt;
                    } else {
                        tk_insert(tv, ti, val, gidx);   // overflow (rare)
                    }
                }
            }
            // drain: warp pays max-lane(cnt) chain executions
            for (int c = 0; c < cnt; ++c)
                tk_insert(tv, ti, cd_v[tid * CDEPTH + c], cd_i[tid * CDEPTH + c]);
        }

        // ---- publish local 21st-best; rebuild per-row threshold
        st_v[tid] = tv[TOPK - 1];
        st_i[tid] = ti[TOPK - 1];
        __syncthreads();   // also protects Bs before next chunk's B-load
        {
            float bv0 = st_v[row6];       int bi0 = st_i[row6];
            #pragma unroll
            for (int q = 1; q < 4; ++q) {
                float cv = st_v[row6 + 64 * q];
                int   ci = st_i[row6 + 64 * q];
                if (better(cv, ci, bv0, bi0)) { bv0 = cv; bi0 = ci; }
            }
            thrv = bv0; thri = bi0;
        }
        __syncthreads();   // st_* reads done before next chunk's publish
    }

    // ---- write partial top-21 for (row, split, quarter)
    const size_t base =
        (((size_t)(rowBase + row6) * NSPLIT + blockIdx.x) * 4 + qd) * TOPK;
    #pragma unroll
    for (int k = 0; k < TOPK; ++k) {
        g_pv[base + k] = tv[k];
        g_pi[base + k] = ti[k];
    }
}

// ---------------- stage 3: merge partials -> global top-21 per row ----------
__global__ __launch_bounds__(256) void merge_kernel(float* __restrict__ out)
{
    __shared__ float sv[256 * TOPK];
    __shared__ int   si[256 * TOPK];
    __shared__ float rv[256];
    __shared__ int   ri[256];
    __shared__ int   ro[256];
    __shared__ int   hp[256];

    const int tid = threadIdx.x;
    const int row = blockIdx.x;
    const int NC  = NSPLIT * 4 * TOPK;       // 3108 candidates per row

    float tv[TOPK];
    int   ti[TOPK];
    #pragma unroll
    for (int k = 0; k < TOPK; ++k) { tv[k] = -FLT_MAX; ti[k] = INT_MAX; }

    const size_t rbase = (size_t)row * NC;
    for (int c = tid; c < NC; c += 256)
        tk_insert(tv, ti, g_pv[rbase + c], g_pi[rbase + c]);

    #pragma unroll
    for (int k = 0; k < TOPK; ++k) {
        sv[tid * TOPK + k] = tv[k];
        si[tid * TOPK + k] = ti[k];
    }
    hp[tid] = 0;
    __syncthreads();

    for (int sel = 0; sel < TOPK; ++sel) {
        const int p = hp[tid];
        rv[tid] = sv[tid * TOPK + p];
        ri[tid] = si[tid * TOPK + p];
        ro[tid] = tid;
        __syncthreads();
        for (int s = 128; s > 0; s >>= 1) {
            if (tid < s) {
                if (better(rv[tid + s], ri[tid + s], rv[tid], ri[tid])) {
                    rv[tid] = rv[tid + s];
                    ri[tid] = ri[tid + s];
                    ro[tid] = ro[tid + s];
                }
            }
            __syncthreads();
        }
        if (tid == 0) {
            out[row * TOPK + sel] = rv[0];                               // values
            out[(size_t)BATCH * TOPK + row * TOPK + sel] = (float)ri[0]; // indices
            hp[ro[0]]++;
        }
        __syncthreads();
    }
}

// ---------------- launch -----------------------------------------------------
extern "C" void kernel_launch(void* const* d_in, const int* in_sizes, int n_in,
                              void* d_out, int out_size)
{
    const int*   item_seq     = (const int*)d_in[0];
    const int*   item_seq_len = (const int*)d_in[1];
    const float* emb          = (const float*)d_in[2];
    float*       out          = (float*)d_out;

    cudaFuncSetAttribute(fused_kernel,
                         cudaFuncAttributeMaxDynamicSharedMemorySize,
                         FUSED_SMEM);

    query_kernel<<<BATCH, DIM>>>(item_seq, item_seq_len, emb);
    fused_kernel<<<dim3(NSPLIT, BATCH / ROWT), 256, FUSED_SMEM>>>(emb);
    merge_kernel<<<BATCH, 256>>>(out);
}

// round 12
// speedup vs baseline: 1.4098x; 1.1224x over previous
#include <cuda_runtime.h>
#include <cfloat>
#include <cstdint>
#include <climits>

#define BATCH   4096
#define HIST    50
#define NITEMS  100000
#define DIM     128
#define TOPK    21
#define ROWT    64                         // queries per CTA
#define ITEMT   64                         // items per chunk
#define NCHUNK  1563                       // ceil(100000/64)
#define NSPLIT  37                         // 37*64 = 2368 CTAs = 8 waves @ 2/SM
#define CDEPTH  4                          // per-thread candidate stack depth
#define AS_F    (ROWT * DIM)               // 8192 floats
#define BS_F    (ITEMT * DIM)              // 8192 floats per buffer
#define FUSED_SMEM ((AS_F + 2 * BS_F) * 4) // 96 KB dynamic

// ---------------- static scratch (module-load; no runtime alloc) ------------
__device__ float g_query[BATCH * DIM];                         // 2 MB
__device__ float g_pv[(size_t)BATCH * NSPLIT * 4 * TOPK];      // ~51 MB
__device__ int   g_pi[(size_t)BATCH * NSPLIT * 4 * TOPK];      // ~51 MB

// ---------------- cp.async helpers ------------------------------------------
__device__ __forceinline__ void cpa16(uint32_t dst, const float* src) {
    asm volatile("cp.async.cg.shared.global [%0], [%1], 16;"
                 :: "r"(dst), "l"(src));
}
__device__ __forceinline__ void cp_commit() {
    asm volatile("cp.async.commit_group;");
}
__device__ __forceinline__ void cp_wait1() {
    asm volatile("cp.async.wait_group 1;");
}
__device__ __forceinline__ void cp_wait0() {
    asm volatile("cp.async.wait_group 0;");
}

// ---------------- comparator: matches jax.lax.top_k (val desc, idx asc) -----
__device__ __forceinline__ bool better(float v1, int i1, float v2, int i2) {
    return (v1 > v2) || (v1 == v2 && i1 < i2);
}

// register-resident sorted insert; static indices only (no local-mem spill)
__device__ __forceinline__ void tk_insert(float (&tv)[TOPK], int (&ti)[TOPK],
                                          float v, int idx) {
    if (better(v, idx, tv[TOPK - 1], ti[TOPK - 1])) {
        tv[TOPK - 1] = v; ti[TOPK - 1] = idx;
        #pragma unroll
        for (int k = TOPK - 1; k > 0; --k) {
            bool sw = better(tv[k], ti[k], tv[k - 1], ti[k - 1]);
            float av = sw ? tv[k]     : tv[k - 1];
            float bv = sw ? tv[k - 1] : tv[k];
            int   ai = sw ? ti[k]     : ti[k - 1];
            int   bi = sw ? ti[k - 1] : ti[k];
            tv[k - 1] = av; tv[k] = bv;
            ti[k - 1] = ai; ti[k] = bi;
        }
    }
}

// ---------------- stage 1: masked mean-pool query build ---------------------
__global__ __launch_bounds__(DIM) void query_kernel(
    const int* __restrict__ item_seq,
    const int* __restrict__ item_seq_len,
    const float* __restrict__ emb)
{
    __shared__ int sidx[HIST];
    const int b = blockIdx.x;
    const int d = threadIdx.x;

    if (d < HIST) sidx[d] = item_seq[b * HIST + d];
    __syncthreads();

    const int len = item_seq_len[b];
    float s = 0.f;
    for (int l = 0; l < len; ++l) s += emb[(size_t)sidx[l] * DIM + d];
    const int denom = len > 1 ? len : 1;
    g_query[b * DIM + d] = s / (float)denom;
}

// ---------------- stage 2: fused scores GEMM + partial top-21 ---------------
// CTA: 64 rows x ~42 chunks of 64 items. 256 threads, micro 4x4 (16 accs).
// As [row][k] 32KB loaded once; B double-buffered via cp.async (2 x 32KB)
// with k4 ^ (item>>2) swizzle; scores staged into the current B buffer with
// a row XOR swizzle for a conflict-free scan. Deferred top-k inserts.
__global__ __launch_bounds__(256, 2) void fused_kernel(const float* __restrict__ emb)
{
    extern __shared__ float smem[];
    float* As  = smem;                 // [row][k]
    float* Bs0 = smem + AS_F;          // [item][k-swizzled]
    float* Bs1 = smem + AS_F + BS_F;

    __shared__ float st_v[256];
    __shared__ int   st_i[256];
    __shared__ float cd_v[256 * CDEPTH];
    __shared__ int   cd_i[256 * CDEPTH];

    const int tid  = threadIdx.x;
    const int row6 = tid & 63;         // A-load row / scan row / B-load item
    const int qd   = tid >> 6;         // quarter (0..3): k-quarter / scan quarter
    const int tx   = tid & 15;         // compute: item group (4 items)
    const int ty   = tid >> 4;         // compute: row group (4 rows)
    const int rowBase = blockIdx.y * ROWT;
    const int ls   = row6 >> 2;        // B swizzle group for loads

    const uint32_t bs0Addr = (uint32_t)__cvta_generic_to_shared(Bs0);
    const uint32_t bs1Addr = (uint32_t)__cvta_generic_to_shared(Bs1);

    // ---- load A (queries) once, [row][k] direct layout
    #pragma unroll
    for (int r = 0; r < 8; ++r) {
        const int kf = qd * 32 + r * 4;
        *(float4*)&As[row6 * DIM + kf] =
            *(const float4*)&g_query[(size_t)(rowBase + row6) * DIM + kf];
    }

    float tv[TOPK];
    int   ti[TOPK];
    #pragma unroll
    for (int k = 0; k < TOPK; ++k) { tv[k] = -FLT_MAX; ti[k] = INT_MAX; }

    float thrv = -FLT_MAX;
    int   thri = INT_MAX;

    const int c0 = (blockIdx.x * NCHUNK) / NSPLIT;
    const int c1 = ((blockIdx.x + 1) * NCHUNK) / NSPLIT;

    // ---- prologue: async-load first chunk into buffer 0
    {
        const int gic = min(c0 * ITEMT + row6, NITEMS - 1);
        const float* src = emb + (size_t)gic * DIM;
        const uint32_t dst = bs0Addr + (uint32_t)row6 * (DIM * 4);
        #pragma unroll
        for (int r = 0; r < 8; ++r) {
            const int k4 = qd * 8 + r;
            cpa16(dst + ((uint32_t)(k4 ^ ls) << 4), src + k4 * 4);
        }
    }
    cp_commit();

    for (int ch = c0; ch < c1; ++ch) {
        const int cur = (ch - c0) & 1;
        float* Bc = cur ? Bs1 : Bs0;

        // ---- prefetch next chunk into the other buffer, then wait for cur
        if (ch + 1 < c1) {
            const int gic = min((ch + 1) * ITEMT + row6, NITEMS - 1);
            const float* src = emb + (size_t)gic * DIM;
            const uint32_t dst =
                (cur ? bs0Addr : bs1Addr) + (uint32_t)row6 * (DIM * 4);
            #pragma unroll
            for (int r = 0; r < 8; ++r) {
                const int k4 = qd * 8 + r;
                cpa16(dst + ((uint32_t)(k4 ^ ls) << 4), src + k4 * 4);
            }
            cp_commit();
            cp_wait1();
        } else {
            cp_wait0();
        }
        __syncthreads();   // cur buffer visible to all threads

        // ---- 64x64 fp32 GEMM, micro 4x4, 4 k's per step
        float acc[4][4];
        #pragma unroll
        for (int i = 0; i < 4; ++i)
            #pragma unroll
            for (int j = 0; j < 4; ++j) acc[i][j] = 0.f;

        #pragma unroll 2
        for (int k4 = 0; k4 < 32; ++k4) {
            float4 b4[4], a4[4];
            #pragma unroll
            for (int j = 0; j < 4; ++j)
                b4[j] = *(const float4*)&Bc[(4 * tx + j) * DIM + ((k4 ^ tx) << 2)];
            #pragma unroll
            for (int i = 0; i < 4; ++i)
                a4[i] = *(const float4*)&As[(4 * ty + i) * DIM + (k4 << 2)];

            float av[4][4], bv[4][4];
            #pragma unroll
            for (int i = 0; i < 4; ++i) {
                av[i][0] = a4[i].x; av[i][1] = a4[i].y;
                av[i][2] = a4[i].z; av[i][3] = a4[i].w;
                bv[i][0] = b4[i].x; bv[i][1] = b4[i].y;
                bv[i][2] = b4[i].z; bv[i][3] = b4[i].w;
            }
            #pragma unroll
            for (int kk = 0; kk < 4; ++kk)
                #pragma unroll
                for (int i = 0; i < 4; ++i)
                    #pragma unroll
                    for (int j = 0; j < 4; ++j)
                        acc[i][j] += av[i][kk] * bv[j][kk];
        }
        __syncthreads();   // all Bc reads done; safe to overwrite with scores

        // ---- stage scores into Bc as [item][row ^ f]
        // f(item) = (((item>>2) + (item&3)) & 7) * 8 ; float4-aligned (bits>=3)
        #pragma unroll
        for (int j = 0; j < 4; ++j) {
            const int f   = ((tx + j) & 7) * 8;
            const int rsw = (4 * ty) ^ f;
            *(float4*)&Bc[(4 * tx + j) * ROWT + rsw] =
                make_float4(acc[0][j], acc[1][j], acc[2][j], acc[3][j]);
        }
        __syncthreads();

        // ---- scan: thread owns (row6, quarter qd); conflict-free reads
        const int itemBase = ch * ITEMT;
        if (ch == c0) {
            #pragma unroll 4
            for (int s = 0; s < 16; ++s) {
                const int jj = qd * 16 + s;
                const int f  = (((jj >> 2) + (jj & 3)) & 7) * 8;
                const float val = Bc[jj * ROWT + (row6 ^ f)];
                const int gidx = itemBase + jj;
                if (gidx < NITEMS) tk_insert(tv, ti, val, gidx);
            }
        } else {
            int cnt = 0;
            #pragma unroll 4
            for (int s = 0; s < 16; ++s) {
                const int jj = qd * 16 + s;
                const int f  = (((jj >> 2) + (jj & 3)) & 7) * 8;
                const float val = Bc[jj * ROWT + (row6 ^ f)];
                const int gidx = itemBase + jj;
                if (gidx < NITEMS && better(val, gidx, thrv, thri)) {
                    if (cnt < CDEPTH) {
                        cd_v[tid * CDEPTH + cnt] = val;
                        cd_i[tid * CDEPTH + cnt] = gidx;
                        ++cnt;
                    } else {
                        tk_insert(tv, ti, val, gidx);   // overflow (rare)
                    }
                }
            }
            for (int c = 0; c < cnt; ++c)
                tk_insert(tv, ti, cd_v[tid * CDEPTH + c], cd_i[tid * CDEPTH + c]);
        }

        // ---- publish local 21st-best; rebuild per-row threshold
        st_v[tid] = tv[TOPK - 1];
        st_i[tid] = ti[TOPK - 1];
        __syncthreads();
        {
            float bv0 = st_v[row6];       int bi0 = st_i[row6];
            #pragma unroll
            for (int q = 1; q < 4; ++q) {
                float cv = st_v[row6 + 64 * q];
                int   ci = st_i[row6 + 64 * q];
                if (better(cv, ci, bv0, bi0)) { bv0 = cv; bi0 = ci; }
            }
            thrv = bv0; thri = bi0;
        }
        __syncthreads();   // scan + st reads done before next buffer overwrite
    }

    // ---- write partial top-21 for (row, split, quarter)
    const size_t base =
        (((size_t)(rowBase + row6) * NSPLIT + blockIdx.x) * 4 + qd) * TOPK;
    #pragma unroll
    for (int k = 0; k < TOPK; ++k) {
        g_pv[base + k] = tv[k];
        g_pi[base + k] = ti[k];
    }
}

// ---------------- stage 3: merge partials -> global top-21 per row ----------
__global__ __launch_bounds__(256) void merge_kernel(float* __restrict__ out)
{
    __shared__ float sv[256 * TOPK];
    __shared__ int   si[256 * TOPK];
    __shared__ float rv[256];
    __shared__ int   ri[256];
    __shared__ int   ro[256];
    __shared__ int   hp[256];

    const int tid = threadIdx.x;
    const int row = blockIdx.x;
    const int NC  = NSPLIT * 4 * TOPK;       // 3108 candidates per row

    float tv[TOPK];
    int   ti[TOPK];
    #pragma unroll
    for (int k = 0; k < TOPK; ++k) { tv[k] = -FLT_MAX; ti[k] = INT_MAX; }

    const size_t rbase = (size_t)row * NC;
    for (int c = tid; c < NC; c += 256)
        tk_insert(tv, ti, g_pv[rbase + c], g_pi[rbase + c]);

    #pragma unroll
    for (int k = 0; k < TOPK; ++k) {
        sv[tid * TOPK + k] = tv[k];
        si[tid * TOPK + k] = ti[k];
    }
    hp[tid] = 0;
    __syncthreads();

    for (int sel = 0; sel < TOPK; ++sel) {
        const int p = hp[tid];
        rv[tid] = sv[tid * TOPK + p];
        ri[tid] = si[tid * TOPK + p];
        ro[tid] = tid;
        __syncthreads();
        for (int s = 128; s > 0; s >>= 1) {
            if (tid < s) {
                if (better(rv[tid + s], ri[tid + s], rv[tid], ri[tid])) {
                    rv[tid] = rv[tid + s];
                    ri[tid] = ri[tid + s];
                    ro[tid] = ro[tid + s];
                }
            }
            __syncthreads();
        }
        if (tid == 0) {
            out[row * TOPK + sel] = rv[0];                               // values
            out[(size_t)BATCH * TOPK + row * TOPK + sel] = (float)ri[0]; // indices
            hp[ro[0]]++;
        }
        __syncthreads();
    }
}

// ---------------- launch -----------------------------------------------------
extern "C" void kernel_launch(void* const* d_in, const int* in_sizes, int n_in,
                              void* d_out, int out_size)
{
    const int*   item_seq     = (const int*)d_in[0];
    const int*   item_seq_len = (const int*)d_in[1];
    const float* emb          = (const float*)d_in[2];
    float*       out          = (float*)d_out;

    cudaFuncSetAttribute(fused_kernel,
                         cudaFuncAttributeMaxDynamicSharedMemorySize,
                         FUSED_SMEM);

    query_kernel<<<BATCH, DIM>>>(item_seq, item_seq_len, emb);
    fused_kernel<<<dim3(NSPLIT, BATCH / ROWT), 256, FUSED_SMEM>>>(emb);
    merge_kernel<<<BATCH, 256>>>(out);
}

// round 14
// speedup vs baseline: 3.1541x; 2.2373x over previous
#include <cuda_runtime.h>
#include <cuda_bf16.h>
#include <cfloat>
#include <cstdint>
#include <climits>

#define BATCH   4096
#define HIST    50
#define NITEMS  100000
#define DIM     128
#define TOPK    21
#define CAND    25                          // per (row,half,split) list length
#define MTILE   128                         // queries per CTA
#define NTILE   64                          // items per chunk
#define NTILES  1563                        // ceil(100000/64)
#define NSPLIT  4                           // 4*32 = 128 CTAs
#define NRB     (BATCH / MTILE)             // 32
#define NCROW   (NSPLIT * 2 * CAND)         // 200 candidates per row
#define CDEPTH  4

#define BBUF    16384                       // 64 items x 256 B bf16
#define SC_OFF  (2 * BBUF)                  // scores after the two B buffers
#define DYN_SMEM (SC_OFF + MTILE * NTILE * 4)   // 32768 + 32768 = 65536

// ---------------- static scratch (module-load; no runtime alloc) ------------
__device__ float          g_query[BATCH * DIM];                 // 2 MB
__device__ __nv_bfloat16  g_ebf[(size_t)NITEMS * DIM];          // 25.6 MB
__device__ int            g_pi[(size_t)BATCH * NCROW];          // 3.3 MB

// ---------------- cp.async helpers (compiled OK in R12) ---------------------
__device__ __forceinline__ void cpa16(uint32_t dst, const void* src) {
    asm volatile("cp.async.cg.shared.global [%0], [%1], 16;"
                 :: "r"(dst), "l"(src));
}
__device__ __forceinline__ void cp_commit() {
    asm volatile("cp.async.commit_group;");
}
__device__ __forceinline__ void cp_wait1() {
    asm volatile("cp.async.wait_group 1;");
}
__device__ __forceinline__ void cp_wait0() {
    asm volatile("cp.async.wait_group 0;");
}

// ---------------- comparator: matches jax.lax.top_k (val desc, idx asc) -----
__device__ __forceinline__ bool better(float v1, int i1, float v2, int i2) {
    return (v1 > v2) || (v1 == v2 && i1 < i2);
}

__device__ __forceinline__ void tk_insert(float (&tv)[CAND], int (&ti)[CAND],
                                          float v, int idx) {
    if (better(v, idx, tv[CAND - 1], ti[CAND - 1])) {
        tv[CAND - 1] = v; ti[CAND - 1] = idx;
        #pragma unroll
        for (int k = CAND - 1; k > 0; --k) {
            bool sw = better(tv[k], ti[k], tv[k - 1], ti[k - 1]);
            float av = sw ? tv[k]     : tv[k - 1];
            float bv = sw ? tv[k - 1] : tv[k];
            int   ai = sw ? ti[k]     : ti[k - 1];
            int   bi = sw ? ti[k - 1] : ti[k];
            tv[k - 1] = av; tv[k] = bv;
            ti[k - 1] = ai; ti[k] = bi;
        }
    }
}

// ---------------- stage 1: masked mean-pool query build ---------------------
__global__ __launch_bounds__(DIM) void query_kernel(
    const int* __restrict__ item_seq,
    const int* __restrict__ item_seq_len,
    const float* __restrict__ emb)
{
    __shared__ int sidx[HIST];
    const int b = blockIdx.x;
    const int d = threadIdx.x;
    if (d < HIST) sidx[d] = item_seq[b * HIST + d];
    __syncthreads();
    const int len = item_seq_len[b];
    float s = 0.f;
    for (int l = 0; l < len; ++l) s += emb[(size_t)sidx[l] * DIM + d];
    const int denom = len > 1 ? len : 1;
    g_query[b * DIM + d] = s / (float)denom;
}

// ---------------- stage 1b: emb fp32 -> bf16 --------------------------------
__global__ __launch_bounds__(256) void convert_kernel(const float* __restrict__ emb)
{
    const size_t base = ((size_t)blockIdx.x * 256 + threadIdx.x) * 8;
    float4 a = *(const float4*)(emb + base);
    float4 b = *(const float4*)(emb + base + 4);
    __nv_bfloat162 p0 = __floats2bfloat162_rn(a.x, a.y);
    __nv_bfloat162 p1 = __floats2bfloat162_rn(a.z, a.w);
    __nv_bfloat162 p2 = __floats2bfloat162_rn(b.x, b.y);
    __nv_bfloat162 p3 = __floats2bfloat162_rn(b.z, b.w);
    uint4 o;
    o.x = *(uint32_t*)&p0; o.y = *(uint32_t*)&p1;
    o.z = *(uint32_t*)&p2; o.w = *(uint32_t*)&p3;
    *(uint4*)(g_ebf + base) = o;
}

// ---------------- B tile loader: 64 items x 128 bf16 (256 B/item) -----------
// 16B-chunk XOR swizzle: chunk c stored at c ^ (item & 7). 256 threads,
// thread t loads 4 chunks of item t/4.
__device__ __forceinline__ void load_btile(uint32_t bbase, int tileBase, int tid)
{
    const int it = tid >> 2;
    int gidx = tileBase + it;
    if (gidx > NITEMS - 1) gidx = NITEMS - 1;
    const uint8_t* src = (const uint8_t*)(g_ebf + (size_t)gidx * DIM);
    const uint32_t rowBase = bbase + (uint32_t)it * 256u;
    const uint32_t sw = (uint32_t)(it & 7);
    #pragma unroll
    for (int i = 0; i < 4; ++i) {
        const uint32_t c = (uint32_t)((tid & 3) * 4 + i);
        cpa16(rowBase + ((c ^ sw) << 4), src + c * 16);
    }
}

// ---------------- stage 2: bf16 HMMA selection (top-25 per row-half) --------
// 8 warps; warp w computes rows [16w,16w+16) x 64 items via m16n8k16 bf16 mma.
// A in registers (loaded once), B double-buffered cp.async, scores staged in
// smem [item][row ^ (item&7)*4], scanned with deferred top-25 inserts.
__global__ __launch_bounds__(256, 1) void mma_kernel()
{
    extern __shared__ __align__(16) uint8_t dsm[];
    __shared__ float cd_v[256 * CDEPTH];
    __shared__ int   cd_i[256 * CDEPTH];

    const int tid   = threadIdx.x;
    const int lane  = tid & 31;
    const int wid   = tid >> 5;
    const int split = blockIdx.x;
    const int rowBase = blockIdx.y * MTILE;

    const uint32_t b0a = (uint32_t)__cvta_generic_to_shared(dsm);
    const uint32_t b1a = b0a + BBUF;
    float* Sc = (float*)(dsm + SC_OFF);

    // ---- A fragments: queries -> bf16, resident in registers
    // m16n8k16 A layout: a0:(r0,k0..1) a1:(r0+8,k0..1) a2:(r0,k+8) a3:(r0+8,k+8)
    uint32_t af[8][4];
    {
        const int r0 = rowBase + wid * 16 + (lane >> 2);
        const float* q0 = g_query + (size_t)r0 * DIM;
        const float* q1 = q0 + 8 * DIM;
        #pragma unroll
        for (int ks = 0; ks < 8; ++ks) {
            const int c = ks * 16 + (lane & 3) * 2;
            float2 x0 = *(const float2*)(q0 + c);
            float2 x1 = *(const float2*)(q1 + c);
            float2 x2 = *(const float2*)(q0 + c + 8);
            float2 x3 = *(const float2*)(q1 + c + 8);
            __nv_bfloat162 p0 = __floats2bfloat162_rn(x0.x, x0.y);
            __nv_bfloat162 p1 = __floats2bfloat162_rn(x1.x, x1.y);
            __nv_bfloat162 p2 = __floats2bfloat162_rn(x2.x, x2.y);
            __nv_bfloat162 p3 = __floats2bfloat162_rn(x3.x, x3.y);
            af[ks][0] = *(uint32_t*)&p0;
            af[ks][1] = *(uint32_t*)&p1;
            af[ks][2] = *(uint32_t*)&p2;
            af[ks][3] = *(uint32_t*)&p3;
        }
    }

    float tv[CAND];
    int   ti[CAND];
    #pragma unroll
    for (int k = 0; k < CAND; ++k) { tv[k] = -FLT_MAX; ti[k] = INT_MAX; }

    const int t0 = (split * NTILES) / NSPLIT;
    const int t1 = ((split + 1) * NTILES) / NSPLIT;

    load_btile(b0a, t0 * NTILE, tid);
    cp_commit();

    for (int t = t0; t < t1; ++t) {
        const int par = (t - t0) & 1;
        const uint32_t curB = par ? b1a : b0a;

        if (t + 1 < t1) {
            load_btile(par ? b0a : b1a, (t + 1) * NTILE, tid);
            cp_commit();
            cp_wait1();
        } else {
            cp_wait0();
        }
        __syncthreads();   // cur buffer visible; prev scan done (barrier below)

        // ---- 64 mma: 8 k-steps x 8 item-blocks
        float acc[8][4];
        #pragma unroll
        for (int nb = 0; nb < 8; ++nb)
            #pragma unroll
            for (int q = 0; q < 4; ++q) acc[nb][q] = 0.f;

        const uint32_t itemRow = curB + (uint32_t)(lane >> 2) * 256u;
        const uint32_t sw = (uint32_t)(lane >> 2) & 7u;   // item&7 = lane>>2
        const uint32_t byteIn = (uint32_t)(lane & 3) * 4u;

        #pragma unroll 2
        for (int ks = 0; ks < 8; ++ks) {
            const uint32_t c0 = (uint32_t)(2 * ks);
            #pragma unroll
            for (int nb = 0; nb < 8; ++nb) {
                const uint32_t base = itemRow + (uint32_t)nb * 2048u;
                uint32_t bf0, bf1;
                asm volatile("ld.shared.b32 %0, [%1];" : "=r"(bf0)
                             : "r"(base + ((c0 ^ sw) << 4) + byteIn));
                asm volatile("ld.shared.b32 %0, [%1];" : "=r"(bf1)
                             : "r"(base + (((c0 + 1) ^ sw) << 4) + byteIn));
                asm volatile(
                    "mma.sync.aligned.m16n8k16.row.col.f32.bf16.bf16.f32 "
                    "{%0,%1,%2,%3}, {%4,%5,%6,%7}, {%8,%9}, {%0,%1,%2,%3};"
                    : "+f"(acc[nb][0]), "+f"(acc[nb][1]),
                      "+f"(acc[nb][2]), "+f"(acc[nb][3])
                    : "r"(af[ks][0]), "r"(af[ks][1]),
                      "r"(af[ks][2]), "r"(af[ks][3]),
                      "r"(bf0), "r"(bf1));
            }
        }

        // ---- stage scores: Sc[item][row ^ (item&7)*4] (conflict-free)
        {
            const int r0 = wid * 16 + (lane >> 2);
            const int r1 = r0 + 8;
            #pragma unroll
            for (int nb = 0; nb < 8; ++nb) {
                const int j0 = nb * 8 + (lane & 3) * 2;
                const int j1 = j0 + 1;
                const int f0 = (j0 & 7) * 4;
                const int f1 = (j1 & 7) * 4;
                Sc[j0 * MTILE + (r0 ^ f0)] = acc[nb][0];
                Sc[j1 * MTILE + (r0 ^ f1)] = acc[nb][1];
                Sc[j0 * MTILE + (r1 ^ f0)] = acc[nb][2];
                Sc[j1 * MTILE + (r1 ^ f1)] = acc[nb][3];
            }
        }
        __syncthreads();

        // ---- scan: thread owns (row = tid&127, half = tid>>7), 32 items
        const int row = tid & 127;
        const int hf  = tid >> 7;
        const int itemBase = t * NTILE;
        if (t == t0) {
            #pragma unroll 4
            for (int s = 0; s < 32; ++s) {
                const int j = hf * 32 + s;
                const float val = Sc[j * MTILE + (row ^ ((j & 7) * 4))];
                const int gidx = itemBase + j;
                if (gidx < NITEMS) tk_insert(tv, ti, val, gidx);
            }
        } else {
            int cnt = 0;
            #pragma unroll 4
            for (int s = 0; s < 32; ++s) {
                const int j = hf * 32 + s;
                const float val = Sc[j * MTILE + (row ^ ((j & 7) * 4))];
                const int gidx = itemBase + j;
                if (gidx < NITEMS &&
                    better(val, gidx, tv[CAND - 1], ti[CAND - 1])) {
                    if (cnt < CDEPTH) {
                        cd_v[tid * CDEPTH + cnt] = val;
                        cd_i[tid * CDEPTH + cnt] = gidx;
                        ++cnt;
                    } else {
                        tk_insert(tv, ti, val, gidx);
                    }
                }
            }
            for (int c = 0; c < cnt; ++c)
                tk_insert(tv, ti, cd_v[tid * CDEPTH + c], cd_i[tid * CDEPTH + c]);
        }
        __syncthreads();   // scan reads done before next chunk's score STS
    }

    // ---- write candidate indices for (row, split, half)
    {
        const int row = tid & 127;
        const int hf  = tid >> 7;
        const size_t base =
            (((size_t)(rowBase + row) * NSPLIT + split) * 2 + hf) * CAND;
        #pragma unroll
        for (int k = 0; k < CAND; ++k) g_pi[base + k] = ti[k];
    }
}

// ---------------- stage 3: exact fp32 rescore + final top-21 ----------------
__global__ __launch_bounds__(256) void rescore_kernel(const float* __restrict__ emb,
                                                      float* __restrict__ out)
{
    __shared__ float qs[DIM];
    __shared__ float cv[256];
    __shared__ int   cidx[256];

    const int tid = threadIdx.x;
    const int row = blockIdx.x;

    if (tid < DIM) qs[tid] = g_query[(size_t)row * DIM + tid];
    __syncthreads();

    float dot = -FLT_MAX;
    int   id  = INT_MAX;
    if (tid < NCROW) {
        const int cand = g_pi[(size_t)row * NCROW + tid];
        if (cand >= 0 && cand < NITEMS) {
            id = cand;
            const float* e = emb + (size_t)cand * DIM;
            float acc = 0.f;
            #pragma unroll 8
            for (int k4 = 0; k4 < 32; ++k4) {
                float4 ev = *(const float4*)(e + 4 * k4);
                acc += qs[4 * k4 + 0] * ev.x;
                acc += qs[4 * k4 + 1] * ev.y;
                acc += qs[4 * k4 + 2] * ev.z;
                acc += qs[4 * k4 + 3] * ev.w;
            }
            dot = acc;
        }
    }
    cv[tid] = dot;
    cidx[tid] = id;
    __syncthreads();

    if (tid < 32) {
        for (int sel = 0; sel < TOPK; ++sel) {
            float bv = -FLT_MAX; int bi = INT_MAX; int bs = tid;
            #pragma unroll
            for (int q = 0; q < 8; ++q) {
                const int s = tid + 32 * q;
                const float v = cv[s];
                const int  ii = cidx[s];
                if (better(v, ii, bv, bi)) { bv = v; bi = ii; bs = s; }
            }
            #pragma unroll
            for (int off = 16; off > 0; off >>= 1) {
                const float ov = __shfl_down_sync(0xffffffffu, bv, off);
                const int   oi = __shfl_down_sync(0xffffffffu, bi, off);
                const int   os = __shfl_down_sync(0xffffffffu, bs, off);
                if (better(ov, oi, bv, bi)) { bv = ov; bi = oi; bs = os; }
            }
            bs = __shfl_sync(0xffffffffu, bs, 0);
            if (tid == 0) {
                out[(size_t)row * TOPK + sel] = bv;                           // values
                out[(size_t)BATCH * TOPK + (size_t)row * TOPK + sel] = (float)bi; // indices
            }
            if (tid == 0) { cv[bs] = -FLT_MAX; cidx[bs] = INT_MAX; }
            __syncwarp();
        }
    }
}

// ---------------- launch -----------------------------------------------------
extern "C" void kernel_launch(void* const* d_in, const int* in_sizes, int n_in,
                              void* d_out, int out_size)
{
    const int*   item_seq     = (const int*)d_in[0];
    const int*   item_seq_len = (const int*)d_in[1];
    const float* emb          = (const float*)d_in[2];
    float*       out          = (float*)d_out;

    cudaFuncSetAttribute(mma_kernel,
                         cudaFuncAttributeMaxDynamicSharedMemorySize,
                         DYN_SMEM);

    query_kernel<<<BATCH, DIM>>>(item_seq, item_seq_len, emb);
    convert_kernel<<<(NITEMS * DIM) / (256 * 8), 256>>>(emb);
    mma_kernel<<<dim3(NSPLIT, NRB), 256, DYN_SMEM>>>();
    rescore_kernel<<<BATCH, 256>>>(emb, out);
}

// round 15
// speedup vs baseline: 3.2063x; 1.0166x over previous
#include <cuda_runtime.h>
#include <cuda_bf16.h>
#include <cfloat>
#include <cstdint>
#include <climits>

#define BATCH   4096
#define HIST    50
#define NITEMS  100000
#define DIM     128
#define TOPK    21
#define CAND    25                          // per (row,half,split) list length
#define MTILE   128                         // queries per CTA
#define NTILE   64                          // items per chunk
#define NTILES  1563                        // ceil(100000/64)
#define NSPLIT  4                           // 4*32 = 128 CTAs
#define NRB     (BATCH / MTILE)             // 32
#define NCROW   (NSPLIT * 2 * CAND)         // 200 candidates per row
#define CDEPTH  4

#define BBUF    16384                       // 64 items x 256 B bf16
#define SC_OFF  (2 * BBUF)                  // scores after the two B buffers
#define DYN_SMEM (SC_OFF + MTILE * NTILE * 4)   // 32768 + 32768 = 65536

// ---------------- static scratch (module-load; no runtime alloc) ------------
__device__ float          g_query[BATCH * DIM];                 // 2 MB
__device__ __nv_bfloat16  g_ebf[(size_t)NITEMS * DIM];          // 25.6 MB
__device__ int            g_pi[(size_t)BATCH * NCROW];          // 3.3 MB

// ---------------- cp.async helpers ------------------------------------------
__device__ __forceinline__ void cpa16(uint32_t dst, const void* src) {
    asm volatile("cp.async.cg.shared.global [%0], [%1], 16;"
                 :: "r"(dst), "l"(src));
}
__device__ __forceinline__ void cp_commit() {
    asm volatile("cp.async.commit_group;");
}
__device__ __forceinline__ void cp_wait1() {
    asm volatile("cp.async.wait_group 1;");
}
__device__ __forceinline__ void cp_wait0() {
    asm volatile("cp.async.wait_group 0;");
}

// ---------------- comparator: matches jax.lax.top_k (val desc, idx asc) -----
__device__ __forceinline__ bool better(float v1, int i1, float v2, int i2) {
    return (v1 > v2) || (v1 == v2 && i1 < i2);
}

__device__ __forceinline__ void tk_insert(float (&tv)[CAND], int (&ti)[CAND],
                                          float v, int idx) {
    if (better(v, idx, tv[CAND - 1], ti[CAND - 1])) {
        tv[CAND - 1] = v; ti[CAND - 1] = idx;
        #pragma unroll
        for (int k = CAND - 1; k > 0; --k) {
            bool sw = better(tv[k], ti[k], tv[k - 1], ti[k - 1]);
            float av = sw ? tv[k]     : tv[k - 1];
            float bv = sw ? tv[k - 1] : tv[k];
            int   ai = sw ? ti[k]     : ti[k - 1];
            int   bi = sw ? ti[k - 1] : ti[k];
            tv[k - 1] = av; tv[k] = bv;
            ti[k - 1] = ai; ti[k] = bi;
        }
    }
}

// ---------------- stage 1: masked mean-pool query build ---------------------
__global__ __launch_bounds__(DIM) void query_kernel(
    const int* __restrict__ item_seq,
    const int* __restrict__ item_seq_len,
    const float* __restrict__ emb)
{
    __shared__ int sidx[HIST];
    const int b = blockIdx.x;
    const int d = threadIdx.x;
    if (d < HIST) sidx[d] = item_seq[b * HIST + d];
    __syncthreads();
    const int len = item_seq_len[b];
    float s = 0.f;
    for (int l = 0; l < len; ++l) s += emb[(size_t)sidx[l] * DIM + d];
    const int denom = len > 1 ? len : 1;
    g_query[b * DIM + d] = s / (float)denom;
}

// ---------------- stage 1b: emb fp32 -> bf16 --------------------------------
__global__ __launch_bounds__(256) void convert_kernel(const float* __restrict__ emb)
{
    const size_t base = ((size_t)blockIdx.x * 256 + threadIdx.x) * 8;
    float4 a = *(const float4*)(emb + base);
    float4 b = *(const float4*)(emb + base + 4);
    __nv_bfloat162 p0 = __floats2bfloat162_rn(a.x, a.y);
    __nv_bfloat162 p1 = __floats2bfloat162_rn(a.z, a.w);
    __nv_bfloat162 p2 = __floats2bfloat162_rn(b.x, b.y);
    __nv_bfloat162 p3 = __floats2bfloat162_rn(b.z, b.w);
    uint4 o;
    o.x = *(uint32_t*)&p0; o.y = *(uint32_t*)&p1;
    o.z = *(uint32_t*)&p2; o.w = *(uint32_t*)&p3;
    *(uint4*)(g_ebf + base) = o;
}

// ---------------- B tile loader: 64 items x 128 bf16 (256 B/item) -----------
// 16B-chunk XOR swizzle: chunk c stored at c ^ (item & 7). 256 threads,
// thread t loads 4 chunks of item t/4.
__device__ __forceinline__ void load_btile(uint32_t bbase, int tileBase, int tid)
{
    const int it = tid >> 2;
    int gidx = tileBase + it;
    if (gidx > NITEMS - 1) gidx = NITEMS - 1;
    const uint8_t* src = (const uint8_t*)(g_ebf + (size_t)gidx * DIM);
    const uint32_t rowBase = bbase + (uint32_t)it * 256u;
    const uint32_t sw = (uint32_t)(it & 7);
    #pragma unroll
    for (int i = 0; i < 4; ++i) {
        const uint32_t c = (uint32_t)((tid & 3) * 4 + i);
        cpa16(rowBase + ((c ^ sw) << 4), src + c * 16);
    }
}

// ---------------- stage 2: bf16 HMMA selection (top-25 per row-half) --------
// 8 warps; warp w computes rows [16w,16w+16) x 64 items via m16n8k16 bf16 mma.
// A in registers (loaded once); B fragments via ldmatrix.x4 with a k-step
// register double-buffer so LDS latency hides behind the mma stream.
__global__ __launch_bounds__(256, 1) void mma_kernel()
{
    extern __shared__ __align__(16) uint8_t dsm[];
    __shared__ float cd_v[256 * CDEPTH];
    __shared__ int   cd_i[256 * CDEPTH];

    const int tid   = threadIdx.x;
    const int lane  = tid & 31;
    const int wid   = tid >> 5;
    const int split = blockIdx.x;
    const int rowBase = blockIdx.y * MTILE;

    const uint32_t b0a = (uint32_t)__cvta_generic_to_shared(dsm);
    const uint32_t b1a = b0a + BBUF;
    float* Sc = (float*)(dsm + SC_OFF);

    // ---- A fragments: queries -> bf16, resident in registers
    uint32_t af[8][4];
    {
        const int r0 = rowBase + wid * 16 + (lane >> 2);
        const float* q0 = g_query + (size_t)r0 * DIM;
        const float* q1 = q0 + 8 * DIM;
        #pragma unroll
        for (int ks = 0; ks < 8; ++ks) {
            const int c = ks * 16 + (lane & 3) * 2;
            float2 x0 = *(const float2*)(q0 + c);
            float2 x1 = *(const float2*)(q1 + c);
            float2 x2 = *(const float2*)(q0 + c + 8);
            float2 x3 = *(const float2*)(q1 + c + 8);
            __nv_bfloat162 p0 = __floats2bfloat162_rn(x0.x, x0.y);
            __nv_bfloat162 p1 = __floats2bfloat162_rn(x1.x, x1.y);
            __nv_bfloat162 p2 = __floats2bfloat162_rn(x2.x, x2.y);
            __nv_bfloat162 p3 = __floats2bfloat162_rn(x3.x, x3.y);
            af[ks][0] = *(uint32_t*)&p0;
            af[ks][1] = *(uint32_t*)&p1;
            af[ks][2] = *(uint32_t*)&p2;
            af[ks][3] = *(uint32_t*)&p3;
        }
    }

    // ldmatrix lane geometry: group g = lane>>3 (matrix id), j = lane&7 (row)
    // matrices per x4: m0=(nb0,c0) m1=(nb0,c0+1) m2=(nb1,c0) m3=(nb1,c0+1)
    const int g  = lane >> 3;
    const int jj = lane & 7;
    const uint32_t laneRow = (uint32_t)((((g >> 1) * 8) + jj) * 256);
    const uint32_t cpar = (uint32_t)(g & 1);

    float tv[CAND];
    int   ti[CAND];
    #pragma unroll
    for (int k = 0; k < CAND; ++k) { tv[k] = -FLT_MAX; ti[k] = INT_MAX; }

    const int t0 = (split * NTILES) / NSPLIT;
    const int t1 = ((split + 1) * NTILES) / NSPLIT;

    load_btile(b0a, t0 * NTILE, tid);
    cp_commit();

    for (int t = t0; t < t1; ++t) {
        const int par = (t - t0) & 1;
        const uint32_t curB = par ? b1a : b0a;

        if (t + 1 < t1) {
            load_btile(par ? b0a : b1a, (t + 1) * NTILE, tid);
            cp_commit();
            cp_wait1();
        } else {
            cp_wait0();
        }
        __syncthreads();   // cur buffer visible; prev scan done (barrier below)

        // ---- GEMM: 8 k-steps x 8 item-blocks, B via ldmatrix.x4 (dbl-buf)
        float acc[8][4];
        #pragma unroll
        for (int nb = 0; nb < 8; ++nb)
            #pragma unroll
            for (int q = 0; q < 4; ++q) acc[nb][q] = 0.f;

        uint32_t bfr[2][4][4];

        #define LDM(buf, ks, nbp)                                             \
            { const uint32_t a_ = curB + (uint32_t)((nbp) * 4096) + laneRow + \
                  ((((uint32_t)(2 * (ks)) + cpar) ^ (uint32_t)jj) << 4);      \
              asm volatile("ldmatrix.sync.aligned.m8n8.x4.shared.b16 "        \
                  "{%0,%1,%2,%3}, [%4];"                                      \
                  : "=r"(bfr[buf][nbp][0]), "=r"(bfr[buf][nbp][1]),           \
                    "=r"(bfr[buf][nbp][2]), "=r"(bfr[buf][nbp][3])            \
                  : "r"(a_)); }

        #define MMA(nb, ks, r0_, r1_)                                         \
            asm volatile(                                                     \
                "mma.sync.aligned.m16n8k16.row.col.f32.bf16.bf16.f32 "        \
                "{%0,%1,%2,%3}, {%4,%5,%6,%7}, {%8,%9}, {%0,%1,%2,%3};"       \
                : "+f"(acc[nb][0]), "+f"(acc[nb][1]),                         \
                  "+f"(acc[nb][2]), "+f"(acc[nb][3])                          \
                : "r"(af[ks][0]), "r"(af[ks][1]),                             \
                  "r"(af[ks][2]), "r"(af[ks][3]),                             \
                  "r"(r0_), "r"(r1_))

        LDM(0, 0, 0); LDM(0, 0, 1); LDM(0, 0, 2); LDM(0, 0, 3);
        #pragma unroll
        for (int ks = 0; ks < 8; ++ks) {
            const int cb = ks & 1;
            const int nbuf = cb ^ 1;
            if (ks < 7) {
                LDM(nbuf, ks + 1, 0); LDM(nbuf, ks + 1, 1);
                LDM(nbuf, ks + 1, 2); LDM(nbuf, ks + 1, 3);
            }
            #pragma unroll
            for (int nbp = 0; nbp < 4; ++nbp) {
                MMA(2 * nbp,     ks, bfr[cb][nbp][0], bfr[cb][nbp][1]);
                MMA(2 * nbp + 1, ks, bfr[cb][nbp][2], bfr[cb][nbp][3]);
            }
        }
        #undef LDM
        #undef MMA

        // ---- stage scores: Sc[item][row ^ (item&7)*4] (conflict-free)
        {
            const int r0 = wid * 16 + (lane >> 2);
            const int r1 = r0 + 8;
            #pragma unroll
            for (int nb = 0; nb < 8; ++nb) {
                const int j0 = nb * 8 + (lane & 3) * 2;
                const int j1 = j0 + 1;
                const int f0 = (j0 & 7) * 4;
                const int f1 = (j1 & 7) * 4;
                Sc[j0 * MTILE + (r0 ^ f0)] = acc[nb][0];
                Sc[j1 * MTILE + (r0 ^ f1)] = acc[nb][1];
                Sc[j0 * MTILE + (r1 ^ f0)] = acc[nb][2];
                Sc[j1 * MTILE + (r1 ^ f1)] = acc[nb][3];
            }
        }
        __syncthreads();

        // ---- scan: thread owns (row = tid&127, half = tid>>7), 32 items
        const int row = tid & 127;
        const int hf  = tid >> 7;
        const int itemBase = t * NTILE;
        if (t == t0) {
            #pragma unroll 4
            for (int s = 0; s < 32; ++s) {
                const int j = hf * 32 + s;
                const float val = Sc[j * MTILE + (row ^ ((j & 7) * 4))];
                const int gidx = itemBase + j;
                if (gidx < NITEMS) tk_insert(tv, ti, val, gidx);
            }
        } else {
            int cnt = 0;
            #pragma unroll 4
            for (int s = 0; s < 32; ++s) {
                const int j = hf * 32 + s;
                const float val = Sc[j * MTILE + (row ^ ((j & 7) * 4))];
                const int gidx = itemBase + j;
                if (gidx < NITEMS &&
                    better(val, gidx, tv[CAND - 1], ti[CAND - 1])) {
                    if (cnt < CDEPTH) {
                        cd_v[tid * CDEPTH + cnt] = val;
                        cd_i[tid * CDEPTH + cnt] = gidx;
                        ++cnt;
                    } else {
                        tk_insert(tv, ti, val, gidx);
                    }
                }
            }
            for (int c = 0; c < cnt; ++c)
                tk_insert(tv, ti, cd_v[tid * CDEPTH + c], cd_i[tid * CDEPTH + c]);
        }
        __syncthreads();   // scan reads done before next chunk's score STS
    }

    // ---- write candidate indices for (row, split, half)
    {
        const int row = tid & 127;
        const int hf  = tid >> 7;
        const size_t base =
            (((size_t)(rowBase + row) * NSPLIT + split) * 2 + hf) * CAND;
        #pragma unroll
        for (int k = 0; k < CAND; ++k) g_pi[base + k] = ti[k];
    }
}

// ---------------- stage 3: exact fp32 rescore + final top-21 ----------------
__global__ __launch_bounds__(256) void rescore_kernel(const float* __restrict__ emb,
                                                      float* __restrict__ out)
{
    __shared__ float qs[DIM];
    __shared__ float cv[256];
    __shared__ int   cidx[256];

    const int tid = threadIdx.x;
    const int row = blockIdx.x;

    if (tid < DIM) qs[tid] = g_query[(size_t)row * DIM + tid];
    __syncthreads();

    float dot = -FLT_MAX;
    int   id  = INT_MAX;
    if (tid < NCROW) {
        const int cand = g_pi[(size_t)row * NCROW + tid];
        if (cand >= 0 && cand < NITEMS) {
            id = cand;
            const float* e = emb + (size_t)cand * DIM;
            float acc = 0.f;
            #pragma unroll 8
            for (int k4 = 0; k4 < 32; ++k4) {
                float4 ev = *(const float4*)(e + 4 * k4);
                acc += qs[4 * k4 + 0] * ev.x;
                acc += qs[4 * k4 + 1] * ev.y;
                acc += qs[4 * k4 + 2] * ev.z;
                acc += qs[4 * k4 + 3] * ev.w;
            }
            dot = acc;
        }
    }
    cv[tid] = dot;
    cidx[tid] = id;
    __syncthreads();

    if (tid < 32) {
        for (int sel = 0; sel < TOPK; ++sel) {
            float bv = -FLT_MAX; int bi = INT_MAX; int bs = tid;
            #pragma unroll
            for (int q = 0; q < 8; ++q) {
                const int s = tid + 32 * q;
                const float v = cv[s];
                const int  ii = cidx[s];
                if (better(v, ii, bv, bi)) { bv = v; bi = ii; bs = s; }
            }
            #pragma unroll
            for (int off = 16; off > 0; off >>= 1) {
                const float ov = __shfl_down_sync(0xffffffffu, bv, off);
                const int   oi = __shfl_down_sync(0xffffffffu, bi, off);
                const int   os = __shfl_down_sync(0xffffffffu, bs, off);
                if (better(ov, oi, bv, bi)) { bv = ov; bi = oi; bs = os; }
            }
            bs = __shfl_sync(0xffffffffu, bs, 0);
            if (tid == 0) {
                out[(size_t)row * TOPK + sel] = bv;                           // values
                out[(size_t)BATCH * TOPK + (size_t)row * TOPK + sel] = (float)bi; // indices
            }
            if (tid == 0) { cv[bs] = -FLT_MAX; cidx[bs] = INT_MAX; }
            __syncwarp();
        }
    }
}

// ---------------- launch -----------------------------------------------------
extern "C" void kernel_launch(void* const* d_in, const int* in_sizes, int n_in,
                              void* d_out, int out_size)
{
    const int*   item_seq     = (const int*)d_in[0];
    const int*   item_seq_len = (const int*)d_in[1];
    const float* emb          = (const float*)d_in[2];
    float*       out          = (float*)d_out;

    cudaFuncSetAttribute(mma_kernel,
                         cudaFuncAttributeMaxDynamicSharedMemorySize,
                         DYN_SMEM);

    query_kernel<<<BATCH, DIM>>>(item_seq, item_seq_len, emb);
    convert_kernel<<<(NITEMS * DIM) / (256 * 8), 256>>>(emb);
    mma_kernel<<<dim3(NSPLIT, NRB), 256, DYN_SMEM>>>();
    rescore_kernel<<<BATCH, 256>>>(emb, out);
}

// round 16
// speedup vs baseline: 4.7089x; 1.4687x over previous
#include <cuda_runtime.h>
#include <cuda_bf16.h>
#include <cfloat>
#include <cstdint>
#include <climits>

#define BATCH   4096
#define HIST    50
#define NITEMS  100000
#define DIM     128
#define TOPK    21
#define CAND    25                          // per (row,half,split) list length
#define MTILE   128                         // queries per CTA
#define NTILE   128                         // items per chunk
#define NTILES  782                         // ceil(100000/128)
#define NSPLIT  4                           // 4*32 = 128 CTAs
#define NRB     (BATCH / MTILE)             // 32
#define NCROW   (NSPLIT * 2 * CAND)         // 200 candidates per row
#define CDEPTH  6

#define BBUF    32768                       // 128 items x 256 B bf16
#define SC_OFF  (2 * BBUF)                                  // 65536
#define CV_OFF  (SC_OFF + MTILE * NTILE * 4)                // 131072
#define CI_OFF  (CV_OFF + 256 * CAND * 4)                   // 156672
#define CDV_OFF (CI_OFF + 256 * CAND * 4)                   // 182272
#define CDI_OFF (CDV_OFF + 256 * CDEPTH * 4)                // 188416
#define DYN_SMEM (CDI_OFF + 256 * CDEPTH * 4)               // 194560

// ---------------- static scratch (module-load; no runtime alloc) ------------
__device__ float          g_query[BATCH * DIM];                 // 2 MB
__device__ __nv_bfloat16  g_ebf[(size_t)NITEMS * DIM];          // 25.6 MB
__device__ int            g_pi[(size_t)BATCH * NCROW];          // 3.3 MB

// ---------------- cp.async helpers ------------------------------------------
__device__ __forceinline__ void cpa16(uint32_t dst, const void* src) {
    asm volatile("cp.async.cg.shared.global [%0], [%1], 16;"
                 :: "r"(dst), "l"(src));
}
__device__ __forceinline__ void cp_commit() {
    asm volatile("cp.async.commit_group;");
}
__device__ __forceinline__ void cp_wait1() {
    asm volatile("cp.async.wait_group 1;");
}
__device__ __forceinline__ void cp_wait0() {
    asm volatile("cp.async.wait_group 0;");
}

// ---------------- comparator: matches jax.lax.top_k (val desc, idx asc) -----
__device__ __forceinline__ bool better(float v1, int i1, float v2, int i2) {
    return (v1 > v2) || (v1 == v2 && i1 < i2);
}

// ---------------- profiler-alignment no-op ----------------------------------
__global__ void nop_kernel() {}

// ---------------- stage 1: masked mean-pool query build ---------------------
__global__ __launch_bounds__(DIM) void query_kernel(
    const int* __restrict__ item_seq,
    const int* __restrict__ item_seq_len,
    const float* __restrict__ emb)
{
    __shared__ int sidx[HIST];
    const int b = blockIdx.x;
    const int d = threadIdx.x;
    if (d < HIST) sidx[d] = item_seq[b * HIST + d];
    __syncthreads();
    const int len = item_seq_len[b];
    float s = 0.f;
    for (int l = 0; l < len; ++l) s += emb[(size_t)sidx[l] * DIM + d];
    const int denom = len > 1 ? len : 1;
    g_query[b * DIM + d] = s / (float)denom;
}

// ---------------- stage 1b: emb fp32 -> bf16 --------------------------------
__global__ __launch_bounds__(256) void convert_kernel(const float* __restrict__ emb)
{
    const size_t base = ((size_t)blockIdx.x * 256 + threadIdx.x) * 8;
    float4 a = *(const float4*)(emb + base);
    float4 b = *(const float4*)(emb + base + 4);
    __nv_bfloat162 p0 = __floats2bfloat162_rn(a.x, a.y);
    __nv_bfloat162 p1 = __floats2bfloat162_rn(a.z, a.w);
    __nv_bfloat162 p2 = __floats2bfloat162_rn(b.x, b.y);
    __nv_bfloat162 p3 = __floats2bfloat162_rn(b.z, b.w);
    uint4 o;
    o.x = *(uint32_t*)&p0; o.y = *(uint32_t*)&p1;
    o.z = *(uint32_t*)&p2; o.w = *(uint32_t*)&p3;
    *(uint4*)(g_ebf + base) = o;
}

// ---------------- B tile loader: 128 items x 128 bf16 (256 B/item) ----------
// 16B-chunk XOR swizzle: chunk c stored at c ^ (item & 7). 256 threads,
// thread t loads 8 chunks of item t/2.
__device__ __forceinline__ void load_btile(uint32_t bbase, int tileBase, int tid)
{
    const int it = tid >> 1;
    int gidx = tileBase + it;
    if (gidx > NITEMS - 1) gidx = NITEMS - 1;
    const uint8_t* src = (const uint8_t*)(g_ebf + (size_t)gidx * DIM);
    const uint32_t rowBase = bbase + (uint32_t)it * 256u;
    const uint32_t sw = (uint32_t)(it & 7);
    const uint32_t c0 = (uint32_t)((tid & 1) * 8);
    #pragma unroll
    for (int i = 0; i < 8; ++i) {
        const uint32_t c = c0 + i;
        cpa16(rowBase + ((c ^ sw) << 4), src + c * 16);
    }
}

// ---------------- stage 2: bf16 HMMA selection (top-25 per row-half) --------
// 8 warps; warp w computes rows [16w,16w+16) x 128 items via m16n8k16 mma.
// Per-thread top-25 kept as an UNSORTED smem list + register min: insert =
// overwrite worst slot + independent 25-wide rescan (no serial swap chain).
__global__ __launch_bounds__(256, 1) void mma_kernel()
{
    extern __shared__ __align__(16) uint8_t dsm[];

    const int tid   = threadIdx.x;
    const int lane  = tid & 31;
    const int wid   = tid >> 5;
    const int split = blockIdx.x;
    const int rowBase = blockIdx.y * MTILE;

    const uint32_t b0a = (uint32_t)__cvta_generic_to_shared(dsm);
    const uint32_t b1a = b0a + BBUF;
    float* Sc   = (float*)(dsm + SC_OFF);
    float* cv_s = (float*)(dsm + CV_OFF);
    int*   ci_s = (int*)(dsm + CI_OFF);
    float* cd_v = (float*)(dsm + CDV_OFF);
    int*   cd_i = (int*)(dsm + CDI_OFF);

    // ---- A fragments: queries -> bf16, resident in registers
    uint32_t af[8][4];
    {
        const int r0 = rowBase + wid * 16 + (lane >> 2);
        const float* q0 = g_query + (size_t)r0 * DIM;
        const float* q1 = q0 + 8 * DIM;
        #pragma unroll
        for (int ks = 0; ks < 8; ++ks) {
            const int c = ks * 16 + (lane & 3) * 2;
            float2 x0 = *(const float2*)(q0 + c);
            float2 x1 = *(const float2*)(q1 + c);
            float2 x2 = *(const float2*)(q0 + c + 8);
            float2 x3 = *(const float2*)(q1 + c + 8);
            __nv_bfloat162 p0 = __floats2bfloat162_rn(x0.x, x0.y);
            __nv_bfloat162 p1 = __floats2bfloat162_rn(x1.x, x1.y);
            __nv_bfloat162 p2 = __floats2bfloat162_rn(x2.x, x2.y);
            __nv_bfloat162 p3 = __floats2bfloat162_rn(x3.x, x3.y);
            af[ks][0] = *(uint32_t*)&p0;
            af[ks][1] = *(uint32_t*)&p1;
            af[ks][2] = *(uint32_t*)&p2;
            af[ks][3] = *(uint32_t*)&p3;
        }
    }

    // ldmatrix lane geometry (validated in R15)
    const int g  = lane >> 3;
    const int jj = lane & 7;
    const uint32_t laneRow = (uint32_t)((((g >> 1) * 8) + jj) * 256);
    const uint32_t cpar = (uint32_t)(g & 1);

    // ---- candidate list init: 25 slots of (-inf, INT_MAX)
    #pragma unroll
    for (int k = 0; k < CAND; ++k) {
        cv_s[k * 256 + tid] = -FLT_MAX;
        ci_s[k * 256 + tid] = INT_MAX;
    }
    float thrv = -FLT_MAX;          // current worst of the 25
    int   thri = INT_MAX;
    int   thrp = 0;                 // its slot

    const int t0 = (split * NTILES) / NSPLIT;
    const int t1 = ((split + 1) * NTILES) / NSPLIT;

    load_btile(b0a, t0 * NTILE, tid);
    cp_commit();

    for (int t = t0; t < t1; ++t) {
        const int par = (t - t0) & 1;
        const uint32_t curB = par ? b1a : b0a;

        if (t + 1 < t1) {
            load_btile(par ? b0a : b1a, (t + 1) * NTILE, tid);
            cp_commit();
            cp_wait1();
        } else {
            cp_wait0();
        }
        __syncthreads();   // cur B visible to all warps

        // ---- GEMM: 8 k-steps x 16 item-blocks
        float acc[16][4];
        #pragma unroll
        for (int nb = 0; nb < 16; ++nb)
            #pragma unroll
            for (int q = 0; q < 4; ++q) acc[nb][q] = 0.f;

        uint32_t bfr[8][4];

        #pragma unroll
        for (int ks = 0; ks < 8; ++ks) {
            #pragma unroll
            for (int nbp = 0; nbp < 8; ++nbp) {
                const uint32_t a_ = curB + (uint32_t)(nbp * 4096) + laneRow +
                    ((((uint32_t)(2 * ks) + cpar) ^ (uint32_t)jj) << 4);
                asm volatile("ldmatrix.sync.aligned.m8n8.x4.shared.b16 "
                    "{%0,%1,%2,%3}, [%4];"
                    : "=r"(bfr[nbp][0]), "=r"(bfr[nbp][1]),
                      "=r"(bfr[nbp][2]), "=r"(bfr[nbp][3])
                    : "r"(a_));
            }
            #pragma unroll
            for (int nbp = 0; nbp < 8; ++nbp) {
                asm volatile(
                    "mma.sync.aligned.m16n8k16.row.col.f32.bf16.bf16.f32 "
                    "{%0,%1,%2,%3}, {%4,%5,%6,%7}, {%8,%9}, {%0,%1,%2,%3};"
                    : "+f"(acc[2*nbp][0]), "+f"(acc[2*nbp][1]),
                      "+f"(acc[2*nbp][2]), "+f"(acc[2*nbp][3])
                    : "r"(af[ks][0]), "r"(af[ks][1]),
                      "r"(af[ks][2]), "r"(af[ks][3]),
                      "r"(bfr[nbp][0]), "r"(bfr[nbp][1]));
                asm volatile(
                    "mma.sync.aligned.m16n8k16.row.col.f32.bf16.bf16.f32 "
                    "{%0,%1,%2,%3}, {%4,%5,%6,%7}, {%8,%9}, {%0,%1,%2,%3};"
                    : "+f"(acc[2*nbp+1][0]), "+f"(acc[2*nbp+1][1]),
                      "+f"(acc[2*nbp+1][2]), "+f"(acc[2*nbp+1][3])
                    : "r"(af[ks][0]), "r"(af[ks][1]),
                      "r"(af[ks][2]), "r"(af[ks][3]),
                      "r"(bfr[nbp][2]), "r"(bfr[nbp][3]));
            }
        }

        // ---- stage scores: Sc[item][row ^ (item&7)*4] (conflict-free)
        {
            const int r0 = wid * 16 + (lane >> 2);
            const int r1 = r0 + 8;
            #pragma unroll
            for (int nb = 0; nb < 16; ++nb) {
                const int j0 = nb * 8 + (lane & 3) * 2;
                const int j1 = j0 + 1;
                const int f0 = (j0 & 7) * 4;
                const int f1 = (j1 & 7) * 4;
                Sc[j0 * MTILE + (r0 ^ f0)] = acc[nb][0];
                Sc[j1 * MTILE + (r0 ^ f1)] = acc[nb][1];
                Sc[j0 * MTILE + (r1 ^ f0)] = acc[nb][2];
                Sc[j1 * MTILE + (r1 ^ f1)] = acc[nb][3];
            }
        }
        __syncthreads();

        // ---- scan: thread owns (row = tid&127, half = tid>>7), 64 items
        const int srow = tid & 127;
        const int hf   = tid >> 7;
        const int itemBase = t * NTILE;
        int cnt = 0;
        #pragma unroll 4
        for (int s = 0; s < 64; ++s) {
            const int j = hf * 64 + s;
            const float val = Sc[j * MTILE + (srow ^ ((j & 7) * 4))];
            const int gidx = itemBase + j;
            if (gidx < NITEMS && better(val, gidx, thrv, thri)) {
                if (cnt < CDEPTH) {
                    cd_v[cnt * 256 + tid] = val;
                    cd_i[cnt * 256 + tid] = gidx;
                    ++cnt;
                } else {
                    // immediate insert (first chunk / bursts)
                    cv_s[thrp * 256 + tid] = val;
                    ci_s[thrp * 256 + tid] = gidx;
                    float wv = val; int wi = gidx; int wp = thrp;
                    #pragma unroll
                    for (int k = 0; k < CAND; ++k) {
                        const float lv = cv_s[k * 256 + tid];
                        const int   li = ci_s[k * 256 + tid];
                        if (better(wv, wi, lv, li)) { wv = lv; wi = li; wp = k; }
                    }
                    thrv = wv; thri = wi; thrp = wp;
                }
            }
        }
        // drain deferred candidates (max-lane batches)
        for (int c = 0; c < cnt; ++c) {
            const float val = cd_v[c * 256 + tid];
            const int  gidx = cd_i[c * 256 + tid];
            if (better(val, gidx, thrv, thri)) {
                cv_s[thrp * 256 + tid] = val;
                ci_s[thrp * 256 + tid] = gidx;
                float wv = val; int wi = gidx; int wp = thrp;
                #pragma unroll
                for (int k = 0; k < CAND; ++k) {
                    const float lv = cv_s[k * 256 + tid];
                    const int   li = ci_s[k * 256 + tid];
                    if (better(wv, wi, lv, li)) { wv = lv; wi = li; wp = k; }
                }
                thrv = wv; thri = wi; thrp = wp;
            }
        }
        __syncthreads();   // scan reads done before next chunk's score STS
    }

    // ---- write candidate indices for (row, split, half)
    {
        const int srow = tid & 127;
        const int hf   = tid >> 7;
        const size_t base =
            (((size_t)(rowBase + srow) * NSPLIT + split) * 2 + hf) * CAND;
        #pragma unroll
        for (int k = 0; k < CAND; ++k) g_pi[base + k] = ci_s[k * 256 + tid];
    }
}

// ---------------- stage 3: exact fp32 rescore + final top-21 ----------------
__global__ __launch_bounds__(256) void rescore_kernel(const float* __restrict__ emb,
                                                      float* __restrict__ out)
{
    __shared__ float qs[DIM];
    __shared__ float cv[256];
    __shared__ int   cidx[256];

    const int tid = threadIdx.x;
    const int row = blockIdx.x;

    if (tid < DIM) qs[tid] = g_query[(size_t)row * DIM + tid];
    __syncthreads();

    float dot = -FLT_MAX;
    int   id  = INT_MAX;
    if (tid < NCROW) {
        const int cand = g_pi[(size_t)row * NCROW + tid];
        if (cand >= 0 && cand < NITEMS) {
            id = cand;
            const float* e = emb + (size_t)cand * DIM;
            float acc = 0.f;
            #pragma unroll 8
            for (int k4 = 0; k4 < 32; ++k4) {
                float4 ev = *(const float4*)(e + 4 * k4);
                acc += qs[4 * k4 + 0] * ev.x;
                acc += qs[4 * k4 + 1] * ev.y;
                acc += qs[4 * k4 + 2] * ev.z;
                acc += qs[4 * k4 + 3] * ev.w;
            }
            dot = acc;
        }
    }
    cv[tid] = dot;
    cidx[tid] = id;
    __syncthreads();

    if (tid < 32) {
        for (int sel = 0; sel < TOPK; ++sel) {
            float bv = -FLT_MAX; int bi = INT_MAX; int bs = tid;
            #pragma unroll
            for (int q = 0; q < 8; ++q) {
                const int s = tid + 32 * q;
                const float v = cv[s];
                const int  ii = cidx[s];
                if (better(v, ii, bv, bi)) { bv = v; bi = ii; bs = s; }
            }
            #pragma unroll
            for (int off = 16; off > 0; off >>= 1) {
                const float ov = __shfl_down_sync(0xffffffffu, bv, off);
                const int   oi = __shfl_down_sync(0xffffffffu, bi, off);
                const int   os = __shfl_down_sync(0xffffffffu, bs, off);
                if (better(ov, oi, bv, bi)) { bv = ov; bi = oi; bs = os; }
            }
            bs = __shfl_sync(0xffffffffu, bs, 0);
            if (tid == 0) {
                out[(size_t)row * TOPK + sel] = bv;                           // values
                out[(size_t)BATCH * TOPK + (size_t)row * TOPK + sel] = (float)bi; // indices
            }
            if (tid == 0) { cv[bs] = -FLT_MAX; cidx[bs] = INT_MAX; }
            __syncwarp();
        }
    }
}

// ---------------- launch -----------------------------------------------------
extern "C" void kernel_launch(void* const* d_in, const int* in_sizes, int n_in,
                              void* d_out, int out_size)
{
    const int*   item_seq     = (const int*)d_in[0];
    const int*   item_seq_len = (const int*)d_in[1];
    const float* emb          = (const float*)d_in[2];
    float*       out          = (float*)d_out;

    cudaFuncSetAttribute(mma_kernel,
                         cudaFuncAttributeMaxDynamicSharedMemorySize,
                         DYN_SMEM);

    nop_kernel<<<1, 32>>>();   // aligns ncu's "-s 5 -c 1" onto mma_kernel
    query_kernel<<<BATCH, DIM>>>(item_seq, item_seq_len, emb);
    convert_kernel<<<(NITEMS * DIM) / (256 * 8), 256>>>(emb);
    mma_kernel<<<dim3(NSPLIT, NRB), 256, DYN_SMEM>>>();
    rescore_kernel<<<BATCH, 256>>>(emb, out);
}

// round 17
// speedup vs baseline: 5.4298x; 1.1531x over previous
#include <cuda_runtime.h>
#include <cuda_bf16.h>
#include <cfloat>
#include <cstdint>
#include <climits>

#define BATCH   4096
#define HIST    50
#define NITEMS  100000
#define DIM     128
#define TOPK    21
#define CAND    25                          // per (row,half,split) list length
#define MTILE   256                         // queries per CTA
#define NTILE   64                          // items per chunk
#define NTILES  1563                        // ceil(100000/64)
#define NSPLIT  9                           // 9*16 = 144 CTAs (~97% of 148 SMs)
#define NRB     (BATCH / MTILE)             // 16
#define NCROW   (NSPLIT * CAND)             // 225 candidates per row (merged)
#define CDEPTH  4
#define NTHR    512

#define BBUF    16384                       // 64 items x 256 B bf16
#define SC_OFF  (2 * BBUF)                                  // 32768
#define CV_OFF  (SC_OFF + MTILE * NTILE * 4)                // 98304
#define CI_OFF  (CV_OFF + NTHR * CAND * 4)                  // 149504
#define CDV_OFF (CI_OFF + NTHR * CAND * 4)                  // 200704
#define CDI_OFF (CDV_OFF + NTHR * CDEPTH * 4)               // 208896
#define DYN_SMEM (CDI_OFF + NTHR * CDEPTH * 4)              // 217088 (<227KB)

// ---------------- static scratch (module-load; no runtime alloc) ------------
__device__ float          g_query[BATCH * DIM];                 // 2 MB
__device__ __nv_bfloat16  g_ebf[(size_t)NITEMS * DIM];          // 25.6 MB
__device__ int            g_pi[(size_t)BATCH * NCROW];          // 3.7 MB

// ---------------- cp.async helpers ------------------------------------------
__device__ __forceinline__ void cpa16(uint32_t dst, const void* src) {
    asm volatile("cp.async.cg.shared.global [%0], [%1], 16;"
                 :: "r"(dst), "l"(src));
}
__device__ __forceinline__ void cp_commit() {
    asm volatile("cp.async.commit_group;");
}
__device__ __forceinline__ void cp_wait1() {
    asm volatile("cp.async.wait_group 1;");
}
__device__ __forceinline__ void cp_wait0() {
    asm volatile("cp.async.wait_group 0;");
}

// ---------------- comparator: matches jax.lax.top_k (val desc, idx asc) -----
__device__ __forceinline__ bool better(float v1, int i1, float v2, int i2) {
    return (v1 > v2) || (v1 == v2 && i1 < i2);
}

// ---------------- profiler-alignment no-op ----------------------------------
__global__ void nop_kernel() {}

// ---------------- stage 1: masked mean-pool query build ---------------------
__global__ __launch_bounds__(DIM) void query_kernel(
    const int* __restrict__ item_seq,
    const int* __restrict__ item_seq_len,
    const float* __restrict__ emb)
{
    __shared__ int sidx[HIST];
    const int b = blockIdx.x;
    const int d = threadIdx.x;
    if (d < HIST) sidx[d] = item_seq[b * HIST + d];
    __syncthreads();
    const int len = item_seq_len[b];
    float s = 0.f;
    for (int l = 0; l < len; ++l) s += emb[(size_t)sidx[l] * DIM + d];
    const int denom = len > 1 ? len : 1;
    g_query[b * DIM + d] = s / (float)denom;
}

// ---------------- stage 1b: emb fp32 -> bf16 --------------------------------
__global__ __launch_bounds__(256) void convert_kernel(const float* __restrict__ emb)
{
    const size_t base = ((size_t)blockIdx.x * 256 + threadIdx.x) * 8;
    float4 a = *(const float4*)(emb + base);
    float4 b = *(const float4*)(emb + base + 4);
    __nv_bfloat162 p0 = __floats2bfloat162_rn(a.x, a.y);
    __nv_bfloat162 p1 = __floats2bfloat162_rn(a.z, a.w);
    __nv_bfloat162 p2 = __floats2bfloat162_rn(b.x, b.y);
    __nv_bfloat162 p3 = __floats2bfloat162_rn(b.z, b.w);
    uint4 o;
    o.x = *(uint32_t*)&p0; o.y = *(uint32_t*)&p1;
    o.z = *(uint32_t*)&p2; o.w = *(uint32_t*)&p3;
    *(uint4*)(g_ebf + base) = o;
}

// ---------------- B tile loader: 64 items x 128 bf16 (256 B/item) -----------
// 16B-chunk XOR swizzle: chunk c stored at c ^ (item & 7). 512 threads,
// thread t loads 2 chunks of item t/8.
__device__ __forceinline__ void load_btile(uint32_t bbase, int tileBase, int tid)
{
    const int it = tid >> 3;
    int gidx = tileBase + it;
    if (gidx > NITEMS - 1) gidx = NITEMS - 1;
    const uint8_t* src = (const uint8_t*)(g_ebf + (size_t)gidx * DIM);
    const uint32_t rowBase = bbase + (uint32_t)it * 256u;
    const uint32_t sw = (uint32_t)(it & 7);
    const uint32_t c0 = (uint32_t)((tid & 7) * 2);
    #pragma unroll
    for (int i = 0; i < 2; ++i) {
        const uint32_t c = c0 + i;
        cpa16(rowBase + ((c ^ sw) << 4), src + c * 16);
    }
}

// ---------------- stage 2: bf16 HMMA selection ------------------------------
// 16 warps; warp w computes rows [16w,16w+16) x 64 items via m16n8k16 mma.
// Per-thread top-25 as UNSORTED smem list + register min; per-row halves
// merged in-kernel to one top-25 per (row, split).
__global__ __launch_bounds__(NTHR, 1) void mma_kernel()
{
    extern __shared__ __align__(16) uint8_t dsm[];

    const int tid   = threadIdx.x;
    const int lane  = tid & 31;
    const int wid   = tid >> 5;             // 0..15
    const int split = blockIdx.x;
    const int rowBase = blockIdx.y * MTILE;

    const uint32_t b0a = (uint32_t)__cvta_generic_to_shared(dsm);
    const uint32_t b1a = b0a + BBUF;
    float* Sc   = (float*)(dsm + SC_OFF);
    float* cv_s = (float*)(dsm + CV_OFF);
    int*   ci_s = (int*)(dsm + CI_OFF);
    float* cd_v = (float*)(dsm + CDV_OFF);
    int*   cd_i = (int*)(dsm + CDI_OFF);

    // ---- A fragments: queries -> bf16, resident in registers
    uint32_t af[8][4];
    {
        const int r0 = rowBase + wid * 16 + (lane >> 2);
        const float* q0 = g_query + (size_t)r0 * DIM;
        const float* q1 = q0 + 8 * DIM;
        #pragma unroll
        for (int ks = 0; ks < 8; ++ks) {
            const int c = ks * 16 + (lane & 3) * 2;
            float2 x0 = *(const float2*)(q0 + c);
            float2 x1 = *(const float2*)(q1 + c);
            float2 x2 = *(const float2*)(q0 + c + 8);
            float2 x3 = *(const float2*)(q1 + c + 8);
            __nv_bfloat162 p0 = __floats2bfloat162_rn(x0.x, x0.y);
            __nv_bfloat162 p1 = __floats2bfloat162_rn(x1.x, x1.y);
            __nv_bfloat162 p2 = __floats2bfloat162_rn(x2.x, x2.y);
            __nv_bfloat162 p3 = __floats2bfloat162_rn(x3.x, x3.y);
            af[ks][0] = *(uint32_t*)&p0;
            af[ks][1] = *(uint32_t*)&p1;
            af[ks][2] = *(uint32_t*)&p2;
            af[ks][3] = *(uint32_t*)&p3;
        }
    }

    // ldmatrix lane geometry (validated R15/R16)
    const int g  = lane >> 3;
    const int jj = lane & 7;
    const uint32_t laneRow = (uint32_t)((((g >> 1) * 8) + jj) * 256);
    const uint32_t cpar = (uint32_t)(g & 1);

    // ---- candidate list init
    #pragma unroll
    for (int k = 0; k < CAND; ++k) {
        cv_s[k * NTHR + tid] = -FLT_MAX;
        ci_s[k * NTHR + tid] = INT_MAX;
    }
    float thrv = -FLT_MAX;          // current worst of the 25
    int   thri = INT_MAX;
    int   thrp = 0;                 // its slot

    const int t0 = (split * NTILES) / NSPLIT;
    const int t1 = ((split + 1) * NTILES) / NSPLIT;

    load_btile(b0a, t0 * NTILE, tid);
    cp_commit();

    for (int t = t0; t < t1; ++t) {
        const int par = (t - t0) & 1;
        const uint32_t curB = par ? b1a : b0a;

        if (t + 1 < t1) {
            load_btile(par ? b0a : b1a, (t + 1) * NTILE, tid);
            cp_commit();
            cp_wait1();
        } else {
            cp_wait0();
        }
        __syncthreads();   // cur B visible to all warps

        // ---- GEMM: 8 k-steps x 8 item-blocks (64 items)
        float acc[8][4];
        #pragma unroll
        for (int nb = 0; nb < 8; ++nb)
            #pragma unroll
            for (int q = 0; q < 4; ++q) acc[nb][q] = 0.f;

        uint32_t bfr[4][4];

        #pragma unroll
        for (int ks = 0; ks < 8; ++ks) {
            #pragma unroll
            for (int nbp = 0; nbp < 4; ++nbp) {
                const uint32_t a_ = curB + (uint32_t)(nbp * 4096) + laneRow +
                    ((((uint32_t)(2 * ks) + cpar) ^ (uint32_t)jj) << 4);
                asm volatile("ldmatrix.sync.aligned.m8n8.x4.shared.b16 "
                    "{%0,%1,%2,%3}, [%4];"
                    : "=r"(bfr[nbp][0]), "=r"(bfr[nbp][1]),
                      "=r"(bfr[nbp][2]), "=r"(bfr[nbp][3])
                    : "r"(a_));
            }
            #pragma unroll
            for (int nbp = 0; nbp < 4; ++nbp) {
                asm volatile(
                    "mma.sync.aligned.m16n8k16.row.col.f32.bf16.bf16.f32 "
                    "{%0,%1,%2,%3}, {%4,%5,%6,%7}, {%8,%9}, {%0,%1,%2,%3};"
                    : "+f"(acc[2*nbp][0]), "+f"(acc[2*nbp][1]),
                      "+f"(acc[2*nbp][2]), "+f"(acc[2*nbp][3])
                    : "r"(af[ks][0]), "r"(af[ks][1]),
                      "r"(af[ks][2]), "r"(af[ks][3]),
                      "r"(bfr[nbp][0]), "r"(bfr[nbp][1]));
                asm volatile(
                    "mma.sync.aligned.m16n8k16.row.col.f32.bf16.bf16.f32 "
                    "{%0,%1,%2,%3}, {%4,%5,%6,%7}, {%8,%9}, {%0,%1,%2,%3};"
                    : "+f"(acc[2*nbp+1][0]), "+f"(acc[2*nbp+1][1]),
                      "+f"(acc[2*nbp+1][2]), "+f"(acc[2*nbp+1][3])
                    : "r"(af[ks][0]), "r"(af[ks][1]),
                      "r"(af[ks][2]), "r"(af[ks][3]),
                      "r"(bfr[nbp][2]), "r"(bfr[nbp][3]));
            }
        }

        // ---- stage scores: Sc[item][row ^ (item&7)*4] (conflict-free)
        {
            const int r0 = wid * 16 + (lane >> 2);
            const int r1 = r0 + 8;
            #pragma unroll
            for (int nb = 0; nb < 8; ++nb) {
                const int j0 = nb * 8 + (lane & 3) * 2;
                const int j1 = j0 + 1;
                const int f0 = (j0 & 7) * 4;
                const int f1 = (j1 & 7) * 4;
                Sc[j0 * MTILE + (r0 ^ f0)] = acc[nb][0];
                Sc[j1 * MTILE + (r0 ^ f1)] = acc[nb][1];
                Sc[j0 * MTILE + (r1 ^ f0)] = acc[nb][2];
                Sc[j1 * MTILE + (r1 ^ f1)] = acc[nb][3];
            }
        }
        __syncthreads();

        // ---- scan: thread owns (row = tid&255, half = tid>>8), 32 items
        const int srow = tid & 255;
        const int hf   = tid >> 8;
        const int itemBase = t * NTILE;
        int cnt = 0;
        #pragma unroll 4
        for (int s = 0; s < 32; ++s) {
            const int j = hf * 32 + s;
            const float val = Sc[j * MTILE + (srow ^ ((j & 7) * 4))];
            const int gidx = itemBase + j;
            if (gidx < NITEMS && better(val, gidx, thrv, thri)) {
                if (cnt < CDEPTH) {
                    cd_v[cnt * NTHR + tid] = val;
                    cd_i[cnt * NTHR + tid] = gidx;
                    ++cnt;
                } else {
                    cv_s[thrp * NTHR + tid] = val;
                    ci_s[thrp * NTHR + tid] = gidx;
                    float wv = val; int wi = gidx; int wp = thrp;
                    #pragma unroll
                    for (int k = 0; k < CAND; ++k) {
                        const float lv = cv_s[k * NTHR + tid];
                        const int   li = ci_s[k * NTHR + tid];
                        if (better(wv, wi, lv, li)) { wv = lv; wi = li; wp = k; }
                    }
                    thrv = wv; thri = wi; thrp = wp;
                }
            }
        }
        for (int c = 0; c < cnt; ++c) {
            const float val = cd_v[c * NTHR + tid];
            const int  gidx = cd_i[c * NTHR + tid];
            if (better(val, gidx, thrv, thri)) {
                cv_s[thrp * NTHR + tid] = val;
                ci_s[thrp * NTHR + tid] = gidx;
                float wv = val; int wi = gidx; int wp = thrp;
                #pragma unroll
                for (int k = 0; k < CAND; ++k) {
                    const float lv = cv_s[k * NTHR + tid];
                    const int   li = ci_s[k * NTHR + tid];
                    if (better(wv, wi, lv, li)) { wv = lv; wi = li; wp = k; }
                }
                thrv = wv; thri = wi; thrp = wp;
            }
        }
        __syncthreads();   // scan reads done before next chunk's score STS
    }

    // ---- merge halves: top-25 of the 50 entries per (row, split)
    __syncthreads();
    if (tid < MTILE) {
        const int row = tid;
        const size_t base = ((size_t)(rowBase + row) * NSPLIT + split) * CAND;
        for (int sel = 0; sel < CAND; ++sel) {
            float bv = -FLT_MAX; int bi = INT_MAX; int bp = 0;
            #pragma unroll
            for (int k = 0; k < CAND; ++k) {
                const float v0 = cv_s[k * NTHR + row];
                const int   i0 = ci_s[k * NTHR + row];
                const float v1 = cv_s[k * NTHR + row + 256];
                const int   i1 = ci_s[k * NTHR + row + 256];
                if (better(v0, i0, bv, bi)) { bv = v0; bi = i0; bp = k; }
                if (better(v1, i1, bv, bi)) { bv = v1; bi = i1; bp = k + CAND; }
            }
            g_pi[base + sel] = bi;
            if (bp < CAND) {
                cv_s[bp * NTHR + row] = -FLT_MAX;
                ci_s[bp * NTHR + row] = INT_MAX;
            } else {
                cv_s[(bp - CAND) * NTHR + row + 256] = -FLT_MAX;
                ci_s[(bp - CAND) * NTHR + row + 256] = INT_MAX;
            }
        }
    }
}

// ---------------- stage 3: exact fp32 rescore + final top-21 ----------------
__global__ __launch_bounds__(256) void rescore_kernel(const float* __restrict__ emb,
                                                      float* __restrict__ out)
{
    __shared__ float qs[DIM];
    __shared__ float cv[256];
    __shared__ int   cidx[256];

    const int tid = threadIdx.x;
    const int row = blockIdx.x;

    if (tid < DIM) qs[tid] = g_query[(size_t)row * DIM + tid];
    __syncthreads();

    float dot = -FLT_MAX;
    int   id  = INT_MAX;
    if (tid < NCROW) {
        const int cand = g_pi[(size_t)row * NCROW + tid];
        if (cand >= 0 && cand < NITEMS) {
            id = cand;
            const float* e = emb + (size_t)cand * DIM;
            float acc = 0.f;
            #pragma unroll 8
            for (int k4 = 0; k4 < 32; ++k4) {
                float4 ev = *(const float4*)(e + 4 * k4);
                acc += qs[4 * k4 + 0] * ev.x;
                acc += qs[4 * k4 + 1] * ev.y;
                acc += qs[4 * k4 + 2] * ev.z;
                acc += qs[4 * k4 + 3] * ev.w;
            }
            dot = acc;
        }
    }
    cv[tid] = dot;
    cidx[tid] = id;
    __syncthreads();

    if (tid < 32) {
        for (int sel = 0; sel < TOPK; ++sel) {
            float bv = -FLT_MAX; int bi = INT_MAX; int bs = tid;
            #pragma unroll
            for (int q = 0; q < 8; ++q) {
                const int s = tid + 32 * q;
                const float v = cv[s];
                const int  ii = cidx[s];
                if (better(v, ii, bv, bi)) { bv = v; bi = ii; bs = s; }
            }
            #pragma unroll
            for (int off = 16; off > 0; off >>= 1) {
                const float ov = __shfl_down_sync(0xffffffffu, bv, off);
                const int   oi = __shfl_down_sync(0xffffffffu, bi, off);
                const int   os = __shfl_down_sync(0xffffffffu, bs, off);
                if (better(ov, oi, bv, bi)) { bv = ov; bi = oi; bs = os; }
            }
            bs = __shfl_sync(0xffffffffu, bs, 0);
            if (tid == 0) {
                out[(size_t)row * TOPK + sel] = bv;                           // values
                out[(size_t)BATCH * TOPK + (size_t)row * TOPK + sel] = (float)bi; // indices
            }
            if (tid == 0) { cv[bs] = -FLT_MAX; cidx[bs] = INT_MAX; }
            __syncwarp();
        }
    }
}

// ---------------- launch -----------------------------------------------------
extern "C" void kernel_launch(void* const* d_in, const int* in_sizes, int n_in,
                              void* d_out, int out_size)
{
    const int*   item_seq     = (const int*)d_in[0];
    const int*   item_seq_len = (const int*)d_in[1];
    const float* emb          = (const float*)d_in[2];
    float*       out          = (float*)d_out;

    cudaFuncSetAttribute(mma_kernel,
                         cudaFuncAttributeMaxDynamicSharedMemorySize,
                         DYN_SMEM);

    nop_kernel<<<1, 32>>>();   // aligns ncu's "-s 5 -c 1" onto mma_kernel
    query_kernel<<<BATCH, DIM>>>(item_seq, item_seq_len, emb);
    convert_kernel<<<(NITEMS * DIM) / (256 * 8), 256>>>(emb);
    mma_kernel<<<dim3(NSPLIT, NRB), NTHR, DYN_SMEM>>>();
    rescore_kernel<<<BATCH, 256>>>(emb, out);
}